// round 8
// baseline (speedup 1.0000x reference)
#include <cuda_runtime.h>
#include <cuda_fp16.h>
#include <cuda_fp8.h>
#include <math.h>

#define B_ 2
#define N_ 2048
#define C_ 1024
#define H_ 16
#define D_ 64

// Scratch (allocation-free contract: __device__ globals)
__device__ float g_qkv[B_ * N_ * 3 * C_];            // [B,N,3,H,D] as [B*N, 3C]
__device__ float g_scale[64];                        // 448/amax per (b,h,{q,k})
__device__ float g_iscale[64];                       // amax/448
__device__ float g_part[64 * 8];                     // partial amax
__device__ unsigned char g_q8[B_ * H_ * N_ * D_];    // fp8 q, head-major [b,h,n,d]
__device__ unsigned char g_k8[B_ * H_ * N_ * D_];    // fp8 k, head-major
// fp16 hi/lo splits
__device__ __half g_xh[B_ * N_ * C_];
__device__ __half g_xl[B_ * N_ * C_];
__device__ __half g_wqh[C_ * 3 * C_];
__device__ __half g_wql[C_ * 3 * C_];
__device__ __half g_wph[C_ * C_];
__device__ __half g_wpl[C_ * C_];
__device__ __half g_atth[B_ * N_ * C_];
__device__ __half g_attl[B_ * N_ * C_];

struct alignas(8) HH { __half2 a, b; };

// ---------------------------------------------------------------------------
// helpers
// ---------------------------------------------------------------------------
__device__ __forceinline__ void mma_f16(float* d, const unsigned* a, unsigned b0, unsigned b1) {
    asm volatile(
        "mma.sync.aligned.m16n8k16.row.col.f32.f16.f16.f32 "
        "{%0,%1,%2,%3},{%4,%5,%6,%7},{%8,%9},{%0,%1,%2,%3};"
        : "+f"(d[0]), "+f"(d[1]), "+f"(d[2]), "+f"(d[3])
        : "r"(a[0]), "r"(a[1]), "r"(a[2]), "r"(a[3]), "r"(b0), "r"(b1));
}

__device__ __forceinline__ void mma_e4m3(float* d, const unsigned* a, unsigned b0, unsigned b1) {
    asm volatile(
        "mma.sync.aligned.m16n8k32.row.col.f32.e4m3.e4m3.f32 "
        "{%0,%1,%2,%3},{%4,%5,%6,%7},{%8,%9},{%0,%1,%2,%3};"
        : "+f"(d[0]), "+f"(d[1]), "+f"(d[2]), "+f"(d[3])
        : "r"(a[0]), "r"(a[1]), "r"(a[2]), "r"(a[3]), "r"(b0), "r"(b1));
}

__device__ __forceinline__ void ldsm_x2t(unsigned& r0, unsigned& r1, const void* p) {
    unsigned s = (unsigned)__cvta_generic_to_shared(p);
    asm volatile("ldmatrix.sync.aligned.m8n8.x2.trans.shared.b16 {%0,%1}, [%2];"
                 : "=r"(r0), "=r"(r1) : "r"(s));
}

__device__ __forceinline__ void ldsm_x4(unsigned& r0, unsigned& r1, unsigned& r2, unsigned& r3,
                                        const void* p) {
    unsigned s = (unsigned)__cvta_generic_to_shared(p);
    asm volatile("ldmatrix.sync.aligned.m8n8.x4.shared.b16 {%0,%1,%2,%3}, [%4];"
                 : "=r"(r0), "=r"(r1), "=r"(r2), "=r"(r3) : "r"(s));
}

__device__ __forceinline__ void cp16(void* smem, const void* gmem) {
    unsigned s = (unsigned)__cvta_generic_to_shared(smem);
    asm volatile("cp.async.cg.shared.global [%0], [%1], 16;" :: "r"(s), "l"(gmem));
}
#define CP_COMMIT asm volatile("cp.async.commit_group;")
#define CP_WAIT0  asm volatile("cp.async.wait_group 0;")
#define CP_WAIT1  asm volatile("cp.async.wait_group 1;")

// ---------------------------------------------------------------------------
// fp32 -> fp16 hi/lo split (elementwise), vectorized by 4
// ---------------------------------------------------------------------------
__global__ void prep_split(const float* __restrict__ src, __half* __restrict__ hi,
                           __half* __restrict__ lo, int n4) {
    int i = blockIdx.x * blockDim.x + threadIdx.x;
    if (i >= n4) return;
    float4 v = ((const float4*)src)[i];
    __half h0 = __float2half_rn(v.x); float r0 = v.x - __half2float(h0);
    __half h1 = __float2half_rn(v.y); float r1 = v.y - __half2float(h1);
    __half h2 = __float2half_rn(v.z); float r2 = v.z - __half2float(h2);
    __half h3 = __float2half_rn(v.w); float r3 = v.w - __half2float(h3);
    HH hh; hh.a = __halves2half2(h0, h1); hh.b = __halves2half2(h2, h3);
    *(HH*)&hi[(size_t)i * 4] = hh;
    HH ll;
    ll.a = __halves2half2(__float2half_rn(r0), __float2half_rn(r1));
    ll.b = __halves2half2(__float2half_rn(r2), __float2half_rn(r3));
    *(HH*)&lo[(size_t)i * 4] = ll;
}

// ---------------------------------------------------------------------------
// fp16x3 GEMM (AhBh + AhBl + AlBh), 3-stage cp.async ring, ldmatrix fragments.
// Block 128x128, 8 warps (warp tile 32x64), K-step 16. Dynamic smem (63 KB).
// ---------------------------------------------------------------------------
#define ASTR 24     // A tile row stride (halfs)
#define BSTR 136    // B tile row stride (halfs)
#define A_ST (128 * ASTR)   // 3072 halfs per stage
#define B_ST (16 * BSTR)    // 2176 halfs per stage
#define GEMM_SMEM ((3 * (2 * A_ST + 2 * B_ST)) * 2)  // bytes = 62976

template <bool BIAS>
__global__ void __launch_bounds__(256)
gemm_f16x3(const __half* __restrict__ Ahp, const __half* __restrict__ Alp,
           const __half* __restrict__ Bhp, const __half* __restrict__ Blp,
           const float* __restrict__ bias, float* __restrict__ Cm,
           int M, int N, int K) {
    extern __shared__ __half sm[];
    __half* As_h = sm;                     // [3][A_ST]
    __half* As_l = As_h + 3 * A_ST;
    __half* Bs_h = As_l + 3 * A_ST;        // [3][B_ST]
    __half* Bs_l = Bs_h + 3 * B_ST;

    const int bm = blockIdx.y * 128;
    const int bn = blockIdx.x * 128;
    const int tid = threadIdx.x;
    const int wid = tid >> 5, lane = tid & 31;
    const int gid = lane >> 2, tig = lane & 3;
    const int wm = (wid & 3) * 32;
    const int wn = (wid >> 2) * 64;

    const int arow = tid >> 1, ach = (tid & 1) * 8;
    const int brow = tid >> 4, bch = (tid & 15) * 8;
    // ldmatrix A address components
    const int lrow = lane & 15, lcol = (lane >> 4) * 8;

    float acc[2][8][4];
#pragma unroll
    for (int i = 0; i < 2; i++)
#pragma unroll
        for (int j = 0; j < 8; j++)
#pragma unroll
            for (int t = 0; t < 4; t++) acc[i][j][t] = 0.f;

    auto issue = [&](int kt, int st) {
        cp16(&As_h[st * A_ST + arow * ASTR + ach], &Ahp[(size_t)(bm + arow) * K + kt + ach]);
        cp16(&As_l[st * A_ST + arow * ASTR + ach], &Alp[(size_t)(bm + arow) * K + kt + ach]);
        cp16(&Bs_h[st * B_ST + brow * BSTR + bch], &Bhp[(size_t)(kt + brow) * N + bn + bch]);
        cp16(&Bs_l[st * B_ST + brow * BSTR + bch], &Blp[(size_t)(kt + brow) * N + bn + bch]);
    };

    issue(0, 0);  CP_COMMIT;
    issue(16, 1); CP_COMMIT;
    CP_WAIT1;
    __syncthreads();

    int buf = 0;
    for (int kt = 0; kt < K; kt += 16) {
        if (kt + 32 < K) issue(kt + 32, (buf + 2) % 3);
        CP_COMMIT;

        const __half* ah = &As_h[buf * A_ST];
        const __half* al = &As_l[buf * A_ST];
        const __half* bh = &Bs_h[buf * B_ST];
        const __half* bl = &Bs_l[buf * B_ST];

        unsigned Af[2][4], Alf[2][4];
#pragma unroll
        for (int mt = 0; mt < 2; mt++) {
            ldsm_x4(Af[mt][0], Af[mt][1], Af[mt][2], Af[mt][3],
                    &ah[(wm + mt * 16 + lrow) * ASTR + lcol]);
            ldsm_x4(Alf[mt][0], Alf[mt][1], Alf[mt][2], Alf[mt][3],
                    &al[(wm + mt * 16 + lrow) * ASTR + lcol]);
        }
#pragma unroll
        for (int nt = 0; nt < 8; nt++) {
            unsigned bh0, bh1, bl0, bl1;
            ldsm_x2t(bh0, bh1, &bh[lrow * BSTR + wn + nt * 8]);
            ldsm_x2t(bl0, bl1, &bl[lrow * BSTR + wn + nt * 8]);
#pragma unroll
            for (int mt = 0; mt < 2; mt++) {
                mma_f16(acc[mt][nt], Af[mt], bh0, bh1);
                mma_f16(acc[mt][nt], Af[mt], bl0, bl1);
                mma_f16(acc[mt][nt], Alf[mt], bh0, bh1);
            }
        }
        CP_WAIT1;
        __syncthreads();
        buf = (buf + 1) % 3;
    }

#pragma unroll
    for (int mt = 0; mt < 2; mt++)
#pragma unroll
        for (int nt = 0; nt < 8; nt++) {
            int r = bm + wm + mt * 16 + gid;
            int c = bn + wn + nt * 8 + 2 * tig;
            float b0 = 0.f, b1 = 0.f;
            if (BIAS) { b0 = bias[c]; b1 = bias[c + 1]; }
            Cm[(size_t)r * N + c]           = acc[mt][nt][0] + b0;
            Cm[(size_t)r * N + c + 1]       = acc[mt][nt][1] + b1;
            Cm[(size_t)(r + 8) * N + c]     = acc[mt][nt][2] + b0;
            Cm[(size_t)(r + 8) * N + c + 1] = acc[mt][nt][3] + b1;
        }
}

// ---------------------------------------------------------------------------
// amax: two-stage
// ---------------------------------------------------------------------------
__global__ void amax_part() {
    const int part = blockIdx.x;
    const int bw = blockIdx.y;
    const int w = bw & 1;
    const int h = (bw >> 1) & 15;
    const int b = bw >> 5;
    __shared__ float red[256];
    float mx = 0.f;
    const int n0 = part * (N_ / 8);
    for (int i = threadIdx.x; i < (N_ / 8) * D_; i += 256) {
        int n = n0 + (i >> 6), d = i & 63;
        float v = g_qkv[((size_t)(b * N_ + n)) * (3 * C_) + w * C_ + h * D_ + d];
        mx = fmaxf(mx, fabsf(v));
    }
    red[threadIdx.x] = mx;
    __syncthreads();
    for (int s = 128; s; s >>= 1) {
        if (threadIdx.x < s) red[threadIdx.x] = fmaxf(red[threadIdx.x], red[threadIdx.x + s]);
        __syncthreads();
    }
    if (threadIdx.x == 0) g_part[bw * 8 + part] = red[0];
}

__global__ void amax_fin() {
    int bw = threadIdx.x;
    float mx = 0.f;
#pragma unroll
    for (int p = 0; p < 8; p++) mx = fmaxf(mx, g_part[bw * 8 + p]);
    float amax = fmaxf(mx, 1e-12f);
    g_scale[bw]  = 448.f / amax;
    g_iscale[bw] = amax / 448.f;
}

// ---------------------------------------------------------------------------
// fp8 quantize Q,K into head-major byte arrays
// ---------------------------------------------------------------------------
__global__ void quant_kernel() {
    int gid = blockIdx.x * blockDim.x + threadIdx.x;
    if (gid >= B_ * N_ * 2 * (C_ / 4)) return;
    int c4 = (gid & 255) * 4;
    int w  = (gid >> 8) & 1;
    int n  = (gid >> 9) & 2047;
    int b  = gid >> 20;
    int h  = c4 >> 6;
    int d  = c4 & 63;
    int si = (b * 16 + h) * 2 + w;
    float s = g_scale[si];
    size_t base = ((size_t)(b * N_ + n)) * (3 * C_) + w * C_ + c4;
    float4 v = *(const float4*)&g_qkv[base];
    unsigned u0 = __nv_cvt_float_to_fp8(v.x * s, __NV_SATFINITE, __NV_E4M3);
    unsigned u1 = __nv_cvt_float_to_fp8(v.y * s, __NV_SATFINITE, __NV_E4M3);
    unsigned u2 = __nv_cvt_float_to_fp8(v.z * s, __NV_SATFINITE, __NV_E4M3);
    unsigned u3 = __nv_cvt_float_to_fp8(v.w * s, __NV_SATFINITE, __NV_E4M3);
    unsigned word = u0 | (u1 << 8) | (u2 << 16) | (u3 << 24);
    unsigned char* dst = (w == 0) ? g_q8 : g_k8;
    *(unsigned*)&dst[((size_t)((b * 16 + h) * N_ + n)) * 64 + d] = word;
}

// ---------------------------------------------------------------------------
// Tensor-core causal flash attention. QK^T fp8, PV fp16 (m16n8k16).
// Work-balanced: block processes q-tiles {p, 31-p}. Epilogue writes hi/lo halfs.
// ---------------------------------------------------------------------------
#define KSTR 17     // K8 tile row stride in words
#define VSTRH 72    // V tile row stride in halfs
#define PSTRH 72    // P tile row stride in halfs

__global__ void flash_fp8() {
    const int pid = blockIdx.x, h = blockIdx.y, b = blockIdx.z;
    __shared__ unsigned Ks8[64 * KSTR];
    __shared__ __half Vs[64 * VSTRH];
    __shared__ __half Ps[64 * PSTRH];

    const int tid = threadIdx.x;
    const int w = tid >> 5, lane = tid & 31;
    const int gid = lane >> 2, tig = lane & 3;
    const int bh = b * H_ + h;
    const unsigned* q8 = (const unsigned*)(g_q8 + (size_t)bh * N_ * D_);
    const unsigned* k8 = (const unsigned*)(g_k8 + (size_t)bh * N_ * D_);
    const float sc = g_iscale[bh * 2 + 0] * g_iscale[bh * 2 + 1] * 0.125f;

    const int prw0 = (w * 16 + gid) * (PSTRH / 2);
    const int prw1 = (w * 16 + gid + 8) * (PSTRH / 2);
    const int ph0 = (w * 16 + gid) * PSTRH;
    const int ph1 = (w * 16 + gid + 8) * PSTRH;

    for (int rep = 0; rep < 2; rep++) {
        const int qt = rep ? (N_ / 64 - 1 - pid) : pid;
        const int q0 = qt * 64;
        const int r0 = q0 + w * 16 + gid;

        unsigned qa[2][4];
#pragma unroll
        for (int ks = 0; ks < 2; ks++) {
            qa[ks][0] = q8[r0 * 16 + tig + 8 * ks];
            qa[ks][1] = q8[(r0 + 8) * 16 + tig + 8 * ks];
            qa[ks][2] = q8[r0 * 16 + tig + 4 + 8 * ks];
            qa[ks][3] = q8[(r0 + 8) * 16 + tig + 4 + 8 * ks];
        }

        float m0 = -INFINITY, m1 = -INFINITY, l0 = 0.f, l1 = 0.f;
        float o[8][4];
#pragma unroll
        for (int nt = 0; nt < 8; nt++)
#pragma unroll
            for (int e = 0; e < 4; e++) o[nt][e] = 0.f;

        for (int kt = 0; kt <= qt; kt++) {
            const int k0 = kt * 64;
            __syncthreads();
#pragma unroll
            for (int i = tid; i < 64 * 16; i += 128) {
                int rr = i >> 4, wd = i & 15;
                Ks8[rr * KSTR + wd] = k8[(k0 + rr) * 16 + wd];
            }
#pragma unroll
            for (int i = tid; i < 64 * 16; i += 128) {
                int rr = i >> 4, c4 = (i & 15) * 4;
                float4 v = *(const float4*)&g_qkv[((size_t)(b * N_ + k0 + rr)) * (3 * C_) + 2 * C_ + h * D_ + c4];
                HH hh;
                hh.a = __floats2half2_rn(v.x, v.y);
                hh.b = __floats2half2_rn(v.z, v.w);
                *(HH*)&Vs[rr * VSTRH + c4] = hh;
            }
            __syncthreads();

            float s[8][4];
#pragma unroll
            for (int nt = 0; nt < 8; nt++) {
                s[nt][0] = s[nt][1] = s[nt][2] = s[nt][3] = 0.f;
                const int col = nt * 8 + gid;
                unsigned b0 = Ks8[col * KSTR + tig];
                unsigned b1 = Ks8[col * KSTR + tig + 4];
                mma_e4m3(s[nt], qa[0], b0, b1);
                unsigned b2 = Ks8[col * KSTR + tig + 8];
                unsigned b3 = Ks8[col * KSTR + tig + 12];
                mma_e4m3(s[nt], qa[1], b2, b3);
            }
            const bool diag = (kt == qt);
#pragma unroll
            for (int nt = 0; nt < 8; nt++) {
                s[nt][0] *= sc; s[nt][1] *= sc; s[nt][2] *= sc; s[nt][3] *= sc;
                if (diag) {
                    int cl = nt * 8 + 2 * tig;
                    int rl0 = w * 16 + gid, rl1 = rl0 + 8;
                    if (cl > rl0)     s[nt][0] = -1e30f;
                    if (cl + 1 > rl0) s[nt][1] = -1e30f;
                    if (cl > rl1)     s[nt][2] = -1e30f;
                    if (cl + 1 > rl1) s[nt][3] = -1e30f;
                }
            }
            float mx0 = s[0][0], mx1 = s[0][2];
#pragma unroll
            for (int nt = 0; nt < 8; nt++) {
                mx0 = fmaxf(mx0, fmaxf(s[nt][0], s[nt][1]));
                mx1 = fmaxf(mx1, fmaxf(s[nt][2], s[nt][3]));
            }
            mx0 = fmaxf(mx0, __shfl_xor_sync(0xffffffffu, mx0, 1));
            mx0 = fmaxf(mx0, __shfl_xor_sync(0xffffffffu, mx0, 2));
            mx1 = fmaxf(mx1, __shfl_xor_sync(0xffffffffu, mx1, 1));
            mx1 = fmaxf(mx1, __shfl_xor_sync(0xffffffffu, mx1, 2));
            const float mn0 = fmaxf(m0, mx0), mn1 = fmaxf(m1, mx1);
            const float f0 = __expf(m0 - mn0), f1 = __expf(m1 - mn1);
            float sum0 = 0.f, sum1 = 0.f;
#pragma unroll
            for (int nt = 0; nt < 8; nt++) {
                float p0 = __expf(s[nt][0] - mn0);
                float p1 = __expf(s[nt][1] - mn0);
                float p2 = __expf(s[nt][2] - mn1);
                float p3 = __expf(s[nt][3] - mn1);
                sum0 += p0 + p1; sum1 += p2 + p3;
                *(__half2*)&Ps[ph0 + nt * 8 + 2 * tig] = __floats2half2_rn(p0, p1);
                *(__half2*)&Ps[ph1 + nt * 8 + 2 * tig] = __floats2half2_rn(p2, p3);
#pragma unroll
                for (int e = 0; e < 2; e++) { o[nt][e] *= f0; o[nt][e + 2] *= f1; }
            }
            sum0 += __shfl_xor_sync(0xffffffffu, sum0, 1);
            sum0 += __shfl_xor_sync(0xffffffffu, sum0, 2);
            sum1 += __shfl_xor_sync(0xffffffffu, sum1, 1);
            sum1 += __shfl_xor_sync(0xffffffffu, sum1, 2);
            l0 = l0 * f0 + sum0;
            l1 = l1 * f1 + sum1;
            m0 = mn0; m1 = mn1;
            __syncwarp();

            const unsigned* Pw = (const unsigned*)Ps;
#pragma unroll
            for (int kc = 0; kc < 4; kc++) {
                unsigned a[4];
                a[0] = Pw[prw0 + kc * 8 + tig];
                a[1] = Pw[prw1 + kc * 8 + tig];
                a[2] = Pw[prw0 + kc * 8 + tig + 4];
                a[3] = Pw[prw1 + kc * 8 + tig + 4];
#pragma unroll
                for (int nt = 0; nt < 8; nt++) {
                    unsigned b0, b1;
                    ldsm_x2t(b0, b1, &Vs[(kc * 16 + (lane & 15)) * VSTRH + nt * 8]);
                    mma_f16(o[nt], a, b0, b1);
                }
            }
        }

        const float il0 = 1.f / l0, il1 = 1.f / l1;
#pragma unroll
        for (int nt = 0; nt < 8; nt++) {
            size_t c = h * D_ + nt * 8 + 2 * tig;
            size_t i0 = ((size_t)(b * N_ + r0)) * C_ + c;
            size_t i1 = ((size_t)(b * N_ + r0 + 8)) * C_ + c;
            float v0 = o[nt][0] * il0, v1 = o[nt][1] * il0;
            float v2 = o[nt][2] * il1, v3 = o[nt][3] * il1;
            __half h0 = __float2half_rn(v0), h1 = __float2half_rn(v1);
            __half h2 = __float2half_rn(v2), h3 = __float2half_rn(v3);
            *(__half2*)&g_atth[i0] = __halves2half2(h0, h1);
            *(__half2*)&g_atth[i1] = __halves2half2(h2, h3);
            *(__half2*)&g_attl[i0] = __halves2half2(
                __float2half_rn(v0 - __half2float(h0)), __float2half_rn(v1 - __half2float(h1)));
            *(__half2*)&g_attl[i1] = __halves2half2(
                __float2half_rn(v2 - __half2float(h2)), __float2half_rn(v3 - __half2float(h3)));
        }
    }
}

// ---------------------------------------------------------------------------
extern "C" void kernel_launch(void* const* d_in, const int* in_sizes, int n_in,
                              void* d_out, int out_size) {
    const float* x      = (const float*)d_in[0];   // [2,2048,1024]
    const float* w_qkv  = (const float*)d_in[1];   // [1024,3072]
    const float* w_proj = (const float*)d_in[2];   // [1024,1024]
    const float* b_proj = (const float*)d_in[3];   // [1024]
    float* out = (float*)d_out;                    // [2,2048,1024]

    float* qkv_ptr; cudaGetSymbolAddress((void**)&qkv_ptr, g_qkv);
    __half *xh, *xl, *wqh, *wql, *wph, *wpl, *ath, *atl;
    cudaGetSymbolAddress((void**)&xh,  g_xh);
    cudaGetSymbolAddress((void**)&xl,  g_xl);
    cudaGetSymbolAddress((void**)&wqh, g_wqh);
    cudaGetSymbolAddress((void**)&wql, g_wql);
    cudaGetSymbolAddress((void**)&wph, g_wph);
    cudaGetSymbolAddress((void**)&wpl, g_wpl);
    cudaGetSymbolAddress((void**)&ath, g_atth);
    cudaGetSymbolAddress((void**)&atl, g_attl);

    static bool attr_set = false;
    if (!attr_set) {
        cudaFuncSetAttribute(gemm_f16x3<false>, cudaFuncAttributeMaxDynamicSharedMemorySize, GEMM_SMEM);
        cudaFuncSetAttribute(gemm_f16x3<true>,  cudaFuncAttributeMaxDynamicSharedMemorySize, GEMM_SMEM);
        attr_set = true;
    }

    // 0) hi/lo fp16 splits of x, w_qkv, w_proj
    prep_split<<<(B_ * N_ * C_ / 4 + 255) / 256, 256>>>(x, xh, xl, B_ * N_ * C_ / 4);
    prep_split<<<(C_ * 3 * C_ / 4 + 255) / 256, 256>>>(w_qkv, wqh, wql, C_ * 3 * C_ / 4);
    prep_split<<<(C_ * C_ / 4 + 255) / 256, 256>>>(w_proj, wph, wpl, C_ * C_ / 4);

    // 1) QKV GEMM (fp16x3, 3-stage pipeline)
    {
        dim3 grid(3 * C_ / 128, (B_ * N_) / 128);
        gemm_f16x3<false><<<grid, 256, GEMM_SMEM>>>(xh, xl, wqh, wql, nullptr, qkv_ptr,
                                                    B_ * N_, 3 * C_, C_);
    }
    // 2) amax -> scales
    {
        dim3 grid(8, 64);
        amax_part<<<grid, 256>>>();
        amax_fin<<<1, 64>>>();
    }
    // 3) fp8 quantize q,k
    quant_kernel<<<(B_ * N_ * 2 * (C_ / 4) + 255) / 256, 256>>>();
    // 4) tensor-core causal flash attention
    {
        dim3 grid(N_ / 128, H_, B_);
        flash_fp8<<<grid, 128>>>();
    }
    // 5) output projection + bias (fp16x3, 3-stage pipeline)
    {
        dim3 grid(C_ / 128, (B_ * N_) / 128);
        gemm_f16x3<true><<<grid, 256, GEMM_SMEM>>>(ath, atl, wph, wpl, b_proj, out,
                                                   B_ * N_, C_, C_);
    }
}

// round 12
// speedup vs baseline: 1.1210x; 1.1210x over previous
#include <cuda_runtime.h>
#include <cuda_fp16.h>
#include <cuda_fp8.h>
#include <math.h>

#define B_ 2
#define N_ 2048
#define C_ 1024
#define H_ 16
#define D_ 64

// Scratch (allocation-free contract: __device__ globals)
__device__ float g_qkv[B_ * N_ * 3 * C_];            // [B,N,3,H,D] as [B*N, 3C]
__device__ float g_scale[64];                        // 448/amax per (b,h,{q,k})
__device__ float g_iscale[64];                       // amax/448
__device__ float g_part[64 * 8];                     // partial amax
__device__ unsigned char g_q8[B_ * H_ * N_ * D_];    // fp8 q, head-major [b,h,n,d]
__device__ unsigned char g_k8[B_ * H_ * N_ * D_];    // fp8 k, head-major
// fp16 hi/lo splits
__device__ __half g_xh[B_ * N_ * C_];
__device__ __half g_xl[B_ * N_ * C_];
__device__ __half g_wqh[C_ * 3 * C_];
__device__ __half g_wql[C_ * 3 * C_];
__device__ __half g_wph[C_ * C_];
__device__ __half g_wpl[C_ * C_];
__device__ __half g_atth[B_ * N_ * C_];
__device__ __half g_attl[B_ * N_ * C_];

struct alignas(8) HH { __half2 a, b; };

// ---------------------------------------------------------------------------
// helpers
// ---------------------------------------------------------------------------
__device__ __forceinline__ void mma_f16(float* d, const unsigned* a, unsigned b0, unsigned b1) {
    asm volatile(
        "mma.sync.aligned.m16n8k16.row.col.f32.f16.f16.f32 "
        "{%0,%1,%2,%3},{%4,%5,%6,%7},{%8,%9},{%0,%1,%2,%3};"
        : "+f"(d[0]), "+f"(d[1]), "+f"(d[2]), "+f"(d[3])
        : "r"(a[0]), "r"(a[1]), "r"(a[2]), "r"(a[3]), "r"(b0), "r"(b1));
}

__device__ __forceinline__ void mma_e4m3(float* d, const unsigned* a, unsigned b0, unsigned b1) {
    asm volatile(
        "mma.sync.aligned.m16n8k32.row.col.f32.e4m3.e4m3.f32 "
        "{%0,%1,%2,%3},{%4,%5,%6,%7},{%8,%9},{%0,%1,%2,%3};"
        : "+f"(d[0]), "+f"(d[1]), "+f"(d[2]), "+f"(d[3])
        : "r"(a[0]), "r"(a[1]), "r"(a[2]), "r"(a[3]), "r"(b0), "r"(b1));
}

__device__ __forceinline__ void ldsm_x2t(unsigned& r0, unsigned& r1, const void* p) {
    unsigned s = (unsigned)__cvta_generic_to_shared(p);
    asm volatile("ldmatrix.sync.aligned.m8n8.x2.trans.shared.b16 {%0,%1}, [%2];"
                 : "=r"(r0), "=r"(r1) : "r"(s));
}

__device__ __forceinline__ void cp16(void* smem, const void* gmem) {
    unsigned s = (unsigned)__cvta_generic_to_shared(smem);
    asm volatile("cp.async.cg.shared.global [%0], [%1], 16;" :: "r"(s), "l"(gmem));
}
#define CP_COMMIT asm volatile("cp.async.commit_group;")
#define CP_WAIT0  asm volatile("cp.async.wait_group 0;")

// ---------------------------------------------------------------------------
// fp32 -> fp16 hi/lo split (elementwise), vectorized by 4
// ---------------------------------------------------------------------------
__global__ void prep_split(const float* __restrict__ src, __half* __restrict__ hi,
                           __half* __restrict__ lo, int n4) {
    int i = blockIdx.x * blockDim.x + threadIdx.x;
    if (i >= n4) return;
    float4 v = ((const float4*)src)[i];
    __half h0 = __float2half_rn(v.x); float r0 = v.x - __half2float(h0);
    __half h1 = __float2half_rn(v.y); float r1 = v.y - __half2float(h1);
    __half h2 = __float2half_rn(v.z); float r2 = v.z - __half2float(h2);
    __half h3 = __float2half_rn(v.w); float r3 = v.w - __half2float(h3);
    HH hh; hh.a = __halves2half2(h0, h1); hh.b = __halves2half2(h2, h3);
    *(HH*)&hi[(size_t)i * 4] = hh;
    HH ll;
    ll.a = __halves2half2(__float2half_rn(r0), __float2half_rn(r1));
    ll.b = __halves2half2(__float2half_rn(r2), __float2half_rn(r3));
    *(HH*)&lo[(size_t)i * 4] = ll;
}

// ---------------------------------------------------------------------------
// fp16x3 GEMM (AhBh + AhBl + AlBh), 2-stage cp.async double buffer.
// Block 128x128, 8 warps (warp tile 32x64), K-step 16. Proven R7 structure.
// ---------------------------------------------------------------------------
#define ASTR 24     // A tile row stride (halfs)
#define BSTR 136    // B tile row stride (halfs)

template <bool BIAS>
__global__ void __launch_bounds__(256)
gemm_f16x3(const __half* __restrict__ Ahp, const __half* __restrict__ Alp,
           const __half* __restrict__ Bhp, const __half* __restrict__ Blp,
           const float* __restrict__ bias, float* __restrict__ Cm,
           int M, int N, int K) {
    __shared__ __half As_h[2][128 * ASTR], As_l[2][128 * ASTR];
    __shared__ __half Bs_h[2][16 * BSTR], Bs_l[2][16 * BSTR];

    const int bm = blockIdx.y * 128;
    const int bn = blockIdx.x * 128;
    const int tid = threadIdx.x;
    const int wid = tid >> 5, lane = tid & 31;
    const int gid = lane >> 2, tig = lane & 3;
    const int wm = (wid & 3) * 32;
    const int wn = (wid >> 2) * 64;

    const int arow = tid >> 1, ach = (tid & 1) * 8;
    const int brow = tid >> 4, bch = (tid & 15) * 8;

    float acc[2][8][4];
#pragma unroll
    for (int i = 0; i < 2; i++)
#pragma unroll
        for (int j = 0; j < 8; j++)
#pragma unroll
            for (int t = 0; t < 4; t++) acc[i][j][t] = 0.f;

    auto issue = [&](int kt, int buf) {
        cp16(&As_h[buf][arow * ASTR + ach], &Ahp[(size_t)(bm + arow) * K + kt + ach]);
        cp16(&As_l[buf][arow * ASTR + ach], &Alp[(size_t)(bm + arow) * K + kt + ach]);
        cp16(&Bs_h[buf][brow * BSTR + bch], &Bhp[(size_t)(kt + brow) * N + bn + bch]);
        cp16(&Bs_l[buf][brow * BSTR + bch], &Blp[(size_t)(kt + brow) * N + bn + bch]);
    };

    issue(0, 0);
    CP_COMMIT;
    CP_WAIT0;
    __syncthreads();

    int buf = 0;
    for (int kt = 0; kt < K; kt += 16) {
        if (kt + 16 < K) issue(kt + 16, buf ^ 1);
        CP_COMMIT;

        const unsigned* awh = (const unsigned*)As_h[buf];
        const unsigned* awl = (const unsigned*)As_l[buf];
        unsigned Af[2][4], Alf[2][4];
#pragma unroll
        for (int mt = 0; mt < 2; mt++) {
            int r0 = wm + mt * 16 + gid;
            Af[mt][0]  = awh[r0 * 12 + tig];
            Af[mt][1]  = awh[(r0 + 8) * 12 + tig];
            Af[mt][2]  = awh[r0 * 12 + tig + 4];
            Af[mt][3]  = awh[(r0 + 8) * 12 + tig + 4];
            Alf[mt][0] = awl[r0 * 12 + tig];
            Alf[mt][1] = awl[(r0 + 8) * 12 + tig];
            Alf[mt][2] = awl[r0 * 12 + tig + 4];
            Alf[mt][3] = awl[(r0 + 8) * 12 + tig + 4];
        }
#pragma unroll
        for (int nt = 0; nt < 8; nt++) {
            unsigned bh0, bh1, bl0, bl1;
            ldsm_x2t(bh0, bh1, &Bs_h[buf][(lane & 15) * BSTR + wn + nt * 8]);
            ldsm_x2t(bl0, bl1, &Bs_l[buf][(lane & 15) * BSTR + wn + nt * 8]);
#pragma unroll
            for (int mt = 0; mt < 2; mt++) {
                mma_f16(acc[mt][nt], Af[mt],  bh0, bh1);
                mma_f16(acc[mt][nt], Af[mt],  bl0, bl1);
                mma_f16(acc[mt][nt], Alf[mt], bh0, bh1);
            }
        }
        CP_WAIT0;
        __syncthreads();
        buf ^= 1;
    }

#pragma unroll
    for (int mt = 0; mt < 2; mt++)
#pragma unroll
        for (int nt = 0; nt < 8; nt++) {
            int r = bm + wm + mt * 16 + gid;
            int c = bn + wn + nt * 8 + 2 * tig;
            float b0 = 0.f, b1 = 0.f;
            if (BIAS) { b0 = bias[c]; b1 = bias[c + 1]; }
            Cm[(size_t)r * N + c]           = acc[mt][nt][0] + b0;
            Cm[(size_t)r * N + c + 1]       = acc[mt][nt][1] + b1;
            Cm[(size_t)(r + 8) * N + c]     = acc[mt][nt][2] + b0;
            Cm[(size_t)(r + 8) * N + c + 1] = acc[mt][nt][3] + b1;
        }
}

// ---------------------------------------------------------------------------
// amax: two-stage
// ---------------------------------------------------------------------------
__global__ void amax_part() {
    const int part = blockIdx.x;
    const int bw = blockIdx.y;
    const int w = bw & 1;
    const int h = (bw >> 1) & 15;
    const int b = bw >> 5;
    __shared__ float red[256];
    float mx = 0.f;
    const int n0 = part * (N_ / 8);
    for (int i = threadIdx.x; i < (N_ / 8) * D_; i += 256) {
        int n = n0 + (i >> 6), d = i & 63;
        float v = g_qkv[((size_t)(b * N_ + n)) * (3 * C_) + w * C_ + h * D_ + d];
        mx = fmaxf(mx, fabsf(v));
    }
    red[threadIdx.x] = mx;
    __syncthreads();
    for (int s = 128; s; s >>= 1) {
        if (threadIdx.x < s) red[threadIdx.x] = fmaxf(red[threadIdx.x], red[threadIdx.x + s]);
        __syncthreads();
    }
    if (threadIdx.x == 0) g_part[bw * 8 + part] = red[0];
}

__global__ void amax_fin() {
    int bw = threadIdx.x;
    float mx = 0.f;
#pragma unroll
    for (int p = 0; p < 8; p++) mx = fmaxf(mx, g_part[bw * 8 + p]);
    float amax = fmaxf(mx, 1e-12f);
    g_scale[bw]  = 448.f / amax;
    g_iscale[bw] = amax / 448.f;
}

// ---------------------------------------------------------------------------
// fp8 quantize Q,K into head-major byte arrays
// ---------------------------------------------------------------------------
__global__ void quant_kernel() {
    int gid = blockIdx.x * blockDim.x + threadIdx.x;
    if (gid >= B_ * N_ * 2 * (C_ / 4)) return;
    int c4 = (gid & 255) * 4;
    int w  = (gid >> 8) & 1;
    int n  = (gid >> 9) & 2047;
    int b  = gid >> 20;
    int h  = c4 >> 6;
    int d  = c4 & 63;
    int si = (b * 16 + h) * 2 + w;
    float s = g_scale[si];
    size_t base = ((size_t)(b * N_ + n)) * (3 * C_) + w * C_ + c4;
    float4 v = *(const float4*)&g_qkv[base];
    unsigned u0 = __nv_cvt_float_to_fp8(v.x * s, __NV_SATFINITE, __NV_E4M3);
    unsigned u1 = __nv_cvt_float_to_fp8(v.y * s, __NV_SATFINITE, __NV_E4M3);
    unsigned u2 = __nv_cvt_float_to_fp8(v.z * s, __NV_SATFINITE, __NV_E4M3);
    unsigned u3 = __nv_cvt_float_to_fp8(v.w * s, __NV_SATFINITE, __NV_E4M3);
    unsigned word = u0 | (u1 << 8) | (u2 << 16) | (u3 << 24);
    unsigned char* dst = (w == 0) ? g_q8 : g_k8;
    *(unsigned*)&dst[((size_t)((b * 16 + h) * N_ + n)) * 64 + d] = word;
}

// ---------------------------------------------------------------------------
// Tensor-core causal flash attention. QK^T fp8, PV fp16 (m16n8k16).
// Work-balanced: block processes q-tiles {p, 31-p}. Epilogue writes hi/lo halfs.
// ---------------------------------------------------------------------------
#define KSTR 17     // K8 tile row stride in words
#define VSTRH 72    // V tile row stride in halfs
#define PSTRH 72    // P tile row stride in halfs

__global__ void flash_fp8() {
    const int pid = blockIdx.x, h = blockIdx.y, b = blockIdx.z;
    __shared__ unsigned Ks8[64 * KSTR];
    __shared__ __half Vs[64 * VSTRH];
    __shared__ __half Ps[64 * PSTRH];

    const int tid = threadIdx.x;
    const int w = tid >> 5, lane = tid & 31;
    const int gid = lane >> 2, tig = lane & 3;
    const int bh = b * H_ + h;
    const unsigned* q8 = (const unsigned*)(g_q8 + (size_t)bh * N_ * D_);
    const unsigned* k8 = (const unsigned*)(g_k8 + (size_t)bh * N_ * D_);
    const float sc = g_iscale[bh * 2 + 0] * g_iscale[bh * 2 + 1] * 0.125f;

    const int prw0 = (w * 16 + gid) * (PSTRH / 2);
    const int prw1 = (w * 16 + gid + 8) * (PSTRH / 2);
    const int ph0 = (w * 16 + gid) * PSTRH;
    const int ph1 = (w * 16 + gid + 8) * PSTRH;

    for (int rep = 0; rep < 2; rep++) {
        const int qt = rep ? (N_ / 64 - 1 - pid) : pid;
        const int q0 = qt * 64;
        const int r0 = q0 + w * 16 + gid;

        unsigned qa[2][4];
#pragma unroll
        for (int ks = 0; ks < 2; ks++) {
            qa[ks][0] = q8[r0 * 16 + tig + 8 * ks];
            qa[ks][1] = q8[(r0 + 8) * 16 + tig + 8 * ks];
            qa[ks][2] = q8[r0 * 16 + tig + 4 + 8 * ks];
            qa[ks][3] = q8[(r0 + 8) * 16 + tig + 4 + 8 * ks];
        }

        float m0 = -INFINITY, m1 = -INFINITY, l0 = 0.f, l1 = 0.f;
        float o[8][4];
#pragma unroll
        for (int nt = 0; nt < 8; nt++)
#pragma unroll
            for (int e = 0; e < 4; e++) o[nt][e] = 0.f;

        for (int kt = 0; kt <= qt; kt++) {
            const int k0 = kt * 64;
            __syncthreads();
#pragma unroll
            for (int i = tid; i < 64 * 16; i += 128) {
                int rr = i >> 4, wd = i & 15;
                Ks8[rr * KSTR + wd] = k8[(k0 + rr) * 16 + wd];
            }
#pragma unroll
            for (int i = tid; i < 64 * 16; i += 128) {
                int rr = i >> 4, c4 = (i & 15) * 4;
                float4 v = *(const float4*)&g_qkv[((size_t)(b * N_ + k0 + rr)) * (3 * C_) + 2 * C_ + h * D_ + c4];
                HH hh;
                hh.a = __floats2half2_rn(v.x, v.y);
                hh.b = __floats2half2_rn(v.z, v.w);
                *(HH*)&Vs[rr * VSTRH + c4] = hh;
            }
            __syncthreads();

            float s[8][4];
#pragma unroll
            for (int nt = 0; nt < 8; nt++) {
                s[nt][0] = s[nt][1] = s[nt][2] = s[nt][3] = 0.f;
                const int col = nt * 8 + gid;
                unsigned b0 = Ks8[col * KSTR + tig];
                unsigned b1 = Ks8[col * KSTR + tig + 4];
                mma_e4m3(s[nt], qa[0], b0, b1);
                unsigned b2 = Ks8[col * KSTR + tig + 8];
                unsigned b3 = Ks8[col * KSTR + tig + 12];
                mma_e4m3(s[nt], qa[1], b2, b3);
            }
            const bool diag = (kt == qt);
#pragma unroll
            for (int nt = 0; nt < 8; nt++) {
                s[nt][0] *= sc; s[nt][1] *= sc; s[nt][2] *= sc; s[nt][3] *= sc;
                if (diag) {
                    int cl = nt * 8 + 2 * tig;
                    int rl0 = w * 16 + gid, rl1 = rl0 + 8;
                    if (cl > rl0)     s[nt][0] = -1e30f;
                    if (cl + 1 > rl0) s[nt][1] = -1e30f;
                    if (cl > rl1)     s[nt][2] = -1e30f;
                    if (cl + 1 > rl1) s[nt][3] = -1e30f;
                }
            }
            float mx0 = s[0][0], mx1 = s[0][2];
#pragma unroll
            for (int nt = 0; nt < 8; nt++) {
                mx0 = fmaxf(mx0, fmaxf(s[nt][0], s[nt][1]));
                mx1 = fmaxf(mx1, fmaxf(s[nt][2], s[nt][3]));
            }
            mx0 = fmaxf(mx0, __shfl_xor_sync(0xffffffffu, mx0, 1));
            mx0 = fmaxf(mx0, __shfl_xor_sync(0xffffffffu, mx0, 2));
            mx1 = fmaxf(mx1, __shfl_xor_sync(0xffffffffu, mx1, 1));
            mx1 = fmaxf(mx1, __shfl_xor_sync(0xffffffffu, mx1, 2));
            const float mn0 = fmaxf(m0, mx0), mn1 = fmaxf(m1, mx1);
            const float f0 = __expf(m0 - mn0), f1 = __expf(m1 - mn1);
            float sum0 = 0.f, sum1 = 0.f;
#pragma unroll
            for (int nt = 0; nt < 8; nt++) {
                float p0 = __expf(s[nt][0] - mn0);
                float p1 = __expf(s[nt][1] - mn0);
                float p2 = __expf(s[nt][2] - mn1);
                float p3 = __expf(s[nt][3] - mn1);
                sum0 += p0 + p1; sum1 += p2 + p3;
                *(__half2*)&Ps[ph0 + nt * 8 + 2 * tig] = __floats2half2_rn(p0, p1);
                *(__half2*)&Ps[ph1 + nt * 8 + 2 * tig] = __floats2half2_rn(p2, p3);
#pragma unroll
                for (int e = 0; e < 2; e++) { o[nt][e] *= f0; o[nt][e + 2] *= f1; }
            }
            sum0 += __shfl_xor_sync(0xffffffffu, sum0, 1);
            sum0 += __shfl_xor_sync(0xffffffffu, sum0, 2);
            sum1 += __shfl_xor_sync(0xffffffffu, sum1, 1);
            sum1 += __shfl_xor_sync(0xffffffffu, sum1, 2);
            l0 = l0 * f0 + sum0;
            l1 = l1 * f1 + sum1;
            m0 = mn0; m1 = mn1;
            __syncwarp();

            const unsigned* Pw = (const unsigned*)Ps;
#pragma unroll
            for (int kc = 0; kc < 4; kc++) {
                unsigned a[4];
                a[0] = Pw[prw0 + kc * 8 + tig];
                a[1] = Pw[prw1 + kc * 8 + tig];
                a[2] = Pw[prw0 + kc * 8 + tig + 4];
                a[3] = Pw[prw1 + kc * 8 + tig + 4];
#pragma unroll
                for (int nt = 0; nt < 8; nt++) {
                    unsigned b0, b1;
                    ldsm_x2t(b0, b1, &Vs[(kc * 16 + (lane & 15)) * VSTRH + nt * 8]);
                    mma_f16(o[nt], a, b0, b1);
                }
            }
        }

        const float il0 = 1.f / l0, il1 = 1.f / l1;
#pragma unroll
        for (int nt = 0; nt < 8; nt++) {
            size_t c = h * D_ + nt * 8 + 2 * tig;
            size_t i0 = ((size_t)(b * N_ + r0)) * C_ + c;
            size_t i1 = ((size_t)(b * N_ + r0 + 8)) * C_ + c;
            float v0 = o[nt][0] * il0, v1 = o[nt][1] * il0;
            float v2 = o[nt][2] * il1, v3 = o[nt][3] * il1;
            __half h0 = __float2half_rn(v0), h1 = __float2half_rn(v1);
            __half h2 = __float2half_rn(v2), h3 = __float2half_rn(v3);
            *(__half2*)&g_atth[i0] = __halves2half2(h0, h1);
            *(__half2*)&g_atth[i1] = __halves2half2(h2, h3);
            *(__half2*)&g_attl[i0] = __halves2half2(
                __float2half_rn(v0 - __half2float(h0)), __float2half_rn(v1 - __half2float(h1)));
            *(__half2*)&g_attl[i1] = __halves2half2(
                __float2half_rn(v2 - __half2float(h2)), __float2half_rn(v3 - __half2float(h3)));
        }
    }
}

// ---------------------------------------------------------------------------
extern "C" void kernel_launch(void* const* d_in, const int* in_sizes, int n_in,
                              void* d_out, int out_size) {
    const float* x      = (const float*)d_in[0];   // [2,2048,1024]
    const float* w_qkv  = (const float*)d_in[1];   // [1024,3072]
    const float* w_proj = (const float*)d_in[2];   // [1024,1024]
    const float* b_proj = (const float*)d_in[3];   // [1024]
    float* out = (float*)d_out;                    // [2,2048,1024]

    float* qkv_ptr; cudaGetSymbolAddress((void**)&qkv_ptr, g_qkv);
    __half *xh, *xl, *wqh, *wql, *wph, *wpl, *ath, *atl;
    cudaGetSymbolAddress((void**)&xh,  g_xh);
    cudaGetSymbolAddress((void**)&xl,  g_xl);
    cudaGetSymbolAddress((void**)&wqh, g_wqh);
    cudaGetSymbolAddress((void**)&wql, g_wql);
    cudaGetSymbolAddress((void**)&wph, g_wph);
    cudaGetSymbolAddress((void**)&wpl, g_wpl);
    cudaGetSymbolAddress((void**)&ath, g_atth);
    cudaGetSymbolAddress((void**)&atl, g_attl);

    // 0) hi/lo fp16 splits of x, w_qkv, w_proj
    prep_split<<<(B_ * N_ * C_ / 4 + 255) / 256, 256>>>(x, xh, xl, B_ * N_ * C_ / 4);
    prep_split<<<(C_ * 3 * C_ / 4 + 255) / 256, 256>>>(w_qkv, wqh, wql, C_ * 3 * C_ / 4);
    prep_split<<<(C_ * C_ / 4 + 255) / 256, 256>>>(w_proj, wph, wpl, C_ * C_ / 4);

    // 1) QKV GEMM (fp16x3)
    {
        dim3 grid(3 * C_ / 128, (B_ * N_) / 128);
        gemm_f16x3<false><<<grid, 256>>>(xh, xl, wqh, wql, nullptr, qkv_ptr, B_ * N_, 3 * C_, C_);
    }
    // 2) amax -> scales
    {
        dim3 grid(8, 64);
        amax_part<<<grid, 256>>>();
        amax_fin<<<1, 64>>>();
    }
    // 3) fp8 quantize q,k
    quant_kernel<<<(B_ * N_ * 2 * (C_ / 4) + 255) / 256, 256>>>();
    // 4) tensor-core causal flash attention
    {
        dim3 grid(N_ / 128, H_, B_);
        flash_fp8<<<grid, 128>>>();
    }
    // 5) output projection + bias (fp16x3)
    {
        dim3 grid(C_ / 128, (B_ * N_) / 128);
        gemm_f16x3<true><<<grid, 256>>>(ath, atl, wph, wpl, b_proj, out, B_ * N_, C_, C_);
    }
}

// round 13
// speedup vs baseline: 1.5635x; 1.3947x over previous
#include <cuda_runtime.h>
#include <cuda_fp16.h>
#include <cuda_fp8.h>
#include <math.h>

#define B_ 2
#define N_ 2048
#define C_ 1024
#define H_ 16
#define D_ 64

// Scratch (allocation-free contract: __device__ globals)
__device__ float g_qkv[B_ * N_ * 3 * C_];            // [B,N,3,H,D] as [B*N, 3C]
__device__ float g_scale[64];                        // 448/amax per (b,h,{q,k})
__device__ float g_iscale[64];                       // amax/448
__device__ float g_part[64 * 8];                     // partial amax
__device__ __align__(256) unsigned char g_q8[B_ * H_ * N_ * D_];  // fp8 q [b,h,n,d]
__device__ __align__(256) unsigned char g_k8[B_ * H_ * N_ * D_];  // fp8 k [b,h,n,d]
__device__ __align__(256) __half g_v16[B_ * H_ * N_ * D_];        // fp16 v [b,h,n,d]
// fp16 hi/lo splits
__device__ __half g_xh[B_ * N_ * C_];
__device__ __half g_xl[B_ * N_ * C_];
__device__ __half g_wqh[C_ * 3 * C_];
__device__ __half g_wql[C_ * 3 * C_];
__device__ __half g_wph[C_ * C_];
__device__ __half g_wpl[C_ * C_];
__device__ __half g_atth[B_ * N_ * C_];
__device__ __half g_attl[B_ * N_ * C_];

struct alignas(8) HH { __half2 a, b; };

// ---------------------------------------------------------------------------
// helpers
// ---------------------------------------------------------------------------
__device__ __forceinline__ void mma_f16(float* d, const unsigned* a, unsigned b0, unsigned b1) {
    asm volatile(
        "mma.sync.aligned.m16n8k16.row.col.f32.f16.f16.f32 "
        "{%0,%1,%2,%3},{%4,%5,%6,%7},{%8,%9},{%0,%1,%2,%3};"
        : "+f"(d[0]), "+f"(d[1]), "+f"(d[2]), "+f"(d[3])
        : "r"(a[0]), "r"(a[1]), "r"(a[2]), "r"(a[3]), "r"(b0), "r"(b1));
}

__device__ __forceinline__ void mma_e4m3(float* d, const unsigned* a, unsigned b0, unsigned b1) {
    asm volatile(
        "mma.sync.aligned.m16n8k32.row.col.f32.e4m3.e4m3.f32 "
        "{%0,%1,%2,%3},{%4,%5,%6,%7},{%8,%9},{%0,%1,%2,%3};"
        : "+f"(d[0]), "+f"(d[1]), "+f"(d[2]), "+f"(d[3])
        : "r"(a[0]), "r"(a[1]), "r"(a[2]), "r"(a[3]), "r"(b0), "r"(b1));
}

__device__ __forceinline__ void ldsm_x2t(unsigned& r0, unsigned& r1, const void* p) {
    unsigned s = (unsigned)__cvta_generic_to_shared(p);
    asm volatile("ldmatrix.sync.aligned.m8n8.x2.trans.shared.b16 {%0,%1}, [%2];"
                 : "=r"(r0), "=r"(r1) : "r"(s));
}

__device__ __forceinline__ void cp16(void* smem, const void* gmem) {
    unsigned s = (unsigned)__cvta_generic_to_shared(smem);
    asm volatile("cp.async.cg.shared.global [%0], [%1], 16;" :: "r"(s), "l"(gmem));
}
#define CP_COMMIT asm volatile("cp.async.commit_group;")
#define CP_WAIT0  asm volatile("cp.async.wait_group 0;")
#define CP_WAIT1  asm volatile("cp.async.wait_group 1;")

// ---------------------------------------------------------------------------
// fp32 -> fp16 hi/lo split (elementwise), vectorized by 4
// ---------------------------------------------------------------------------
__global__ void prep_split(const float* __restrict__ src, __half* __restrict__ hi,
                           __half* __restrict__ lo, int n4) {
    int i = blockIdx.x * blockDim.x + threadIdx.x;
    if (i >= n4) return;
    float4 v = ((const float4*)src)[i];
    __half h0 = __float2half_rn(v.x); float r0 = v.x - __half2float(h0);
    __half h1 = __float2half_rn(v.y); float r1 = v.y - __half2float(h1);
    __half h2 = __float2half_rn(v.z); float r2 = v.z - __half2float(h2);
    __half h3 = __float2half_rn(v.w); float r3 = v.w - __half2float(h3);
    HH hh; hh.a = __halves2half2(h0, h1); hh.b = __halves2half2(h2, h3);
    *(HH*)&hi[(size_t)i * 4] = hh;
    HH ll;
    ll.a = __halves2half2(__float2half_rn(r0), __float2half_rn(r1));
    ll.b = __halves2half2(__float2half_rn(r2), __float2half_rn(r3));
    *(HH*)&lo[(size_t)i * 4] = ll;
}

// ---------------------------------------------------------------------------
// fp16x3 GEMM (AhBh + AhBl + AlBh), 2-stage cp.async double buffer.
// Block 128x128, 8 warps (warp tile 32x64), K-step 16. Proven R7 structure.
// ---------------------------------------------------------------------------
#define ASTR 24     // A tile row stride (halfs)
#define BSTR 136    // B tile row stride (halfs)

template <bool BIAS>
__global__ void __launch_bounds__(256)
gemm_f16x3(const __half* __restrict__ Ahp, const __half* __restrict__ Alp,
           const __half* __restrict__ Bhp, const __half* __restrict__ Blp,
           const float* __restrict__ bias, float* __restrict__ Cm,
           int M, int N, int K) {
    __shared__ __half As_h[2][128 * ASTR], As_l[2][128 * ASTR];
    __shared__ __half Bs_h[2][16 * BSTR], Bs_l[2][16 * BSTR];

    const int bm = blockIdx.y * 128;
    const int bn = blockIdx.x * 128;
    const int tid = threadIdx.x;
    const int wid = tid >> 5, lane = tid & 31;
    const int gid = lane >> 2, tig = lane & 3;
    const int wm = (wid & 3) * 32;
    const int wn = (wid >> 2) * 64;

    const int arow = tid >> 1, ach = (tid & 1) * 8;
    const int brow = tid >> 4, bch = (tid & 15) * 8;

    float acc[2][8][4];
#pragma unroll
    for (int i = 0; i < 2; i++)
#pragma unroll
        for (int j = 0; j < 8; j++)
#pragma unroll
            for (int t = 0; t < 4; t++) acc[i][j][t] = 0.f;

    auto issue = [&](int kt, int buf) {
        cp16(&As_h[buf][arow * ASTR + ach], &Ahp[(size_t)(bm + arow) * K + kt + ach]);
        cp16(&As_l[buf][arow * ASTR + ach], &Alp[(size_t)(bm + arow) * K + kt + ach]);
        cp16(&Bs_h[buf][brow * BSTR + bch], &Bhp[(size_t)(kt + brow) * N + bn + bch]);
        cp16(&Bs_l[buf][brow * BSTR + bch], &Blp[(size_t)(kt + brow) * N + bn + bch]);
    };

    issue(0, 0);
    CP_COMMIT;
    CP_WAIT0;
    __syncthreads();

    int buf = 0;
    for (int kt = 0; kt < K; kt += 16) {
        if (kt + 16 < K) issue(kt + 16, buf ^ 1);
        CP_COMMIT;

        const unsigned* awh = (const unsigned*)As_h[buf];
        const unsigned* awl = (const unsigned*)As_l[buf];
        unsigned Af[2][4], Alf[2][4];
#pragma unroll
        for (int mt = 0; mt < 2; mt++) {
            int r0 = wm + mt * 16 + gid;
            Af[mt][0]  = awh[r0 * 12 + tig];
            Af[mt][1]  = awh[(r0 + 8) * 12 + tig];
            Af[mt][2]  = awh[r0 * 12 + tig + 4];
            Af[mt][3]  = awh[(r0 + 8) * 12 + tig + 4];
            Alf[mt][0] = awl[r0 * 12 + tig];
            Alf[mt][1] = awl[(r0 + 8) * 12 + tig];
            Alf[mt][2] = awl[r0 * 12 + tig + 4];
            Alf[mt][3] = awl[(r0 + 8) * 12 + tig + 4];
        }
#pragma unroll
        for (int nt = 0; nt < 8; nt++) {
            unsigned bh0, bh1, bl0, bl1;
            ldsm_x2t(bh0, bh1, &Bs_h[buf][(lane & 15) * BSTR + wn + nt * 8]);
            ldsm_x2t(bl0, bl1, &Bs_l[buf][(lane & 15) * BSTR + wn + nt * 8]);
#pragma unroll
            for (int mt = 0; mt < 2; mt++) {
                mma_f16(acc[mt][nt], Af[mt],  bh0, bh1);
                mma_f16(acc[mt][nt], Af[mt],  bl0, bl1);
                mma_f16(acc[mt][nt], Alf[mt], bh0, bh1);
            }
        }
        CP_WAIT0;
        __syncthreads();
        buf ^= 1;
    }

#pragma unroll
    for (int mt = 0; mt < 2; mt++)
#pragma unroll
        for (int nt = 0; nt < 8; nt++) {
            int r = bm + wm + mt * 16 + gid;
            int c = bn + wn + nt * 8 + 2 * tig;
            float b0 = 0.f, b1 = 0.f;
            if (BIAS) { b0 = bias[c]; b1 = bias[c + 1]; }
            Cm[(size_t)r * N + c]           = acc[mt][nt][0] + b0;
            Cm[(size_t)r * N + c + 1]       = acc[mt][nt][1] + b1;
            Cm[(size_t)(r + 8) * N + c]     = acc[mt][nt][2] + b0;
            Cm[(size_t)(r + 8) * N + c + 1] = acc[mt][nt][3] + b1;
        }
}

// ---------------------------------------------------------------------------
// amax: two-stage
// ---------------------------------------------------------------------------
__global__ void amax_part() {
    const int part = blockIdx.x;
    const int bw = blockIdx.y;
    const int w = bw & 1;
    const int h = (bw >> 1) & 15;
    const int b = bw >> 5;
    __shared__ float red[256];
    float mx = 0.f;
    const int n0 = part * (N_ / 8);
    for (int i = threadIdx.x; i < (N_ / 8) * D_; i += 256) {
        int n = n0 + (i >> 6), d = i & 63;
        float v = g_qkv[((size_t)(b * N_ + n)) * (3 * C_) + w * C_ + h * D_ + d];
        mx = fmaxf(mx, fabsf(v));
    }
    red[threadIdx.x] = mx;
    __syncthreads();
    for (int s = 128; s; s >>= 1) {
        if (threadIdx.x < s) red[threadIdx.x] = fmaxf(red[threadIdx.x], red[threadIdx.x + s]);
        __syncthreads();
    }
    if (threadIdx.x == 0) g_part[bw * 8 + part] = red[0];
}

__global__ void amax_fin() {
    int bw = threadIdx.x;
    float mx = 0.f;
#pragma unroll
    for (int p = 0; p < 8; p++) mx = fmaxf(mx, g_part[bw * 8 + p]);
    float amax = fmaxf(mx, 1e-12f);
    g_scale[bw]  = 448.f / amax;
    g_iscale[bw] = amax / 448.f;
}

// ---------------------------------------------------------------------------
// fp8 quantize Q,K into head-major byte arrays
// ---------------------------------------------------------------------------
__global__ void quant_kernel() {
    int gid = blockIdx.x * blockDim.x + threadIdx.x;
    if (gid >= B_ * N_ * 2 * (C_ / 4)) return;
    int c4 = (gid & 255) * 4;
    int w  = (gid >> 8) & 1;
    int n  = (gid >> 9) & 2047;
    int b  = gid >> 20;
    int h  = c4 >> 6;
    int d  = c4 & 63;
    int si = (b * 16 + h) * 2 + w;
    float s = g_scale[si];
    size_t base = ((size_t)(b * N_ + n)) * (3 * C_) + w * C_ + c4;
    float4 v = *(const float4*)&g_qkv[base];
    unsigned u0 = __nv_cvt_float_to_fp8(v.x * s, __NV_SATFINITE, __NV_E4M3);
    unsigned u1 = __nv_cvt_float_to_fp8(v.y * s, __NV_SATFINITE, __NV_E4M3);
    unsigned u2 = __nv_cvt_float_to_fp8(v.z * s, __NV_SATFINITE, __NV_E4M3);
    unsigned u3 = __nv_cvt_float_to_fp8(v.w * s, __NV_SATFINITE, __NV_E4M3);
    unsigned word = u0 | (u1 << 8) | (u2 << 16) | (u3 << 24);
    unsigned char* dst = (w == 0) ? g_q8 : g_k8;
    *(unsigned*)&dst[((size_t)((b * 16 + h) * N_ + n)) * 64 + d] = word;
}

// ---------------------------------------------------------------------------
// V fp32 -> fp16 head-major (one-time conversion; flash loads halfs directly)
// ---------------------------------------------------------------------------
__global__ void conv_v() {
    int gid = blockIdx.x * blockDim.x + threadIdx.x;   // B*N*(C/4) = 1M
    if (gid >= B_ * N_ * (C_ / 4)) return;
    int c4 = (gid & 255) * 4;
    int n  = (gid >> 8) & 2047;
    int b  = gid >> 19;
    int h  = c4 >> 6;
    int d  = c4 & 63;
    float4 v = *(const float4*)&g_qkv[((size_t)(b * N_ + n)) * (3 * C_) + 2 * C_ + c4];
    HH hh;
    hh.a = __floats2half2_rn(v.x, v.y);
    hh.b = __floats2half2_rn(v.z, v.w);
    *(HH*)&g_v16[((size_t)((b * 16 + h) * N_ + n)) * 64 + d] = hh;
}

// ---------------------------------------------------------------------------
// Tensor-core causal flash attention. QK^T fp8, PV fp16.
// cp.async double-buffered K8/V16 tiles; work-balanced pairs {p, 31-p}.
// ---------------------------------------------------------------------------
#define KSTR 20     // K8 tile row stride in words (80B, 16B-aligned, conflict-free)
#define VSTRH 72    // V tile row stride in halfs (144B, 16B-aligned, ldsm-conflict-free)
#define PSTRH 72    // P tile row stride in halfs

__global__ void flash_fp8() {
    const int pid = blockIdx.x, h = blockIdx.y, b = blockIdx.z;
    __shared__ unsigned Ks8[2][64 * KSTR];
    __shared__ __half Vs[2][64 * VSTRH];
    __shared__ __half Ps[64 * PSTRH];

    const int tid = threadIdx.x;
    const int w = tid >> 5, lane = tid & 31;
    const int gid = lane >> 2, tig = lane & 3;
    const int bh = b * H_ + h;
    const unsigned* q8 = (const unsigned*)(g_q8 + (size_t)bh * N_ * D_);
    const unsigned* k8 = (const unsigned*)(g_k8 + (size_t)bh * N_ * D_);
    const __half* v16 = g_v16 + (size_t)bh * N_ * D_;
    const float sc = g_iscale[bh * 2 + 0] * g_iscale[bh * 2 + 1] * 0.125f;

    const int prw0 = (w * 16 + gid) * (PSTRH / 2);
    const int prw1 = (w * 16 + gid + 8) * (PSTRH / 2);
    const int ph0 = (w * 16 + gid) * PSTRH;
    const int ph1 = (w * 16 + gid + 8) * PSTRH;

    // cp.async tile issue: K 256 x 16B chunks, V 512 x 16B chunks
    auto issue = [&](int kt_, int st) {
        const int k0 = kt_ * 64;
#pragma unroll
        for (int l = 0; l < 2; l++) {
            int idx = tid + l * 128;
            int rr = idx >> 2, cc = (idx & 3) * 4;
            cp16(&Ks8[st][rr * KSTR + cc], &k8[(size_t)(k0 + rr) * 16 + cc]);
        }
#pragma unroll
        for (int l = 0; l < 4; l++) {
            int idx = tid + l * 128;
            int rr = idx >> 3, ch = idx & 7;
            cp16(&Vs[st][rr * VSTRH + ch * 8], &v16[(size_t)(k0 + rr) * 64 + ch * 8]);
        }
    };

    for (int rep = 0; rep < 2; rep++) {
        const int qt = rep ? (N_ / 64 - 1 - pid) : pid;
        const int q0 = qt * 64;
        const int r0 = q0 + w * 16 + gid;

        unsigned qa[2][4];
#pragma unroll
        for (int ks = 0; ks < 2; ks++) {
            qa[ks][0] = q8[r0 * 16 + tig + 8 * ks];
            qa[ks][1] = q8[(r0 + 8) * 16 + tig + 8 * ks];
            qa[ks][2] = q8[r0 * 16 + tig + 4 + 8 * ks];
            qa[ks][3] = q8[(r0 + 8) * 16 + tig + 4 + 8 * ks];
        }

        float m0 = -INFINITY, m1 = -INFINITY, l0 = 0.f, l1 = 0.f;
        float o[8][4];
#pragma unroll
        for (int nt = 0; nt < 8; nt++)
#pragma unroll
            for (int e = 0; e < 4; e++) o[nt][e] = 0.f;

        __syncthreads();              // previous rep fully done with both stages
        issue(0, 0);
        CP_COMMIT;

        int st = 0;
        for (int kt = 0; kt <= qt; kt++) {
            if (kt < qt) {
                __syncthreads();      // all warps done computing stage st^1 (prev iter)
                issue(kt + 1, st ^ 1);
                CP_COMMIT;
                CP_WAIT1;             // stage st data landed (next stage may be in flight)
            } else {
                CP_WAIT0;
            }
            __syncthreads();          // stage st visible to all warps

            // ---- S = q8 k8^T (fp8 mma), scale + causal mask ----
            float s[8][4];
#pragma unroll
            for (int nt = 0; nt < 8; nt++) {
                s[nt][0] = s[nt][1] = s[nt][2] = s[nt][3] = 0.f;
                const int col = nt * 8 + gid;
                unsigned b0 = Ks8[st][col * KSTR + tig];
                unsigned b1 = Ks8[st][col * KSTR + tig + 4];
                mma_e4m3(s[nt], qa[0], b0, b1);
                unsigned b2 = Ks8[st][col * KSTR + tig + 8];
                unsigned b3 = Ks8[st][col * KSTR + tig + 12];
                mma_e4m3(s[nt], qa[1], b2, b3);
            }
            const bool diag = (kt == qt);
#pragma unroll
            for (int nt = 0; nt < 8; nt++) {
                s[nt][0] *= sc; s[nt][1] *= sc; s[nt][2] *= sc; s[nt][3] *= sc;
                if (diag) {
                    int cl = nt * 8 + 2 * tig;
                    int rl0 = w * 16 + gid, rl1 = rl0 + 8;
                    if (cl > rl0)     s[nt][0] = -1e30f;
                    if (cl + 1 > rl0) s[nt][1] = -1e30f;
                    if (cl > rl1)     s[nt][2] = -1e30f;
                    if (cl + 1 > rl1) s[nt][3] = -1e30f;
                }
            }
            // ---- online softmax ----
            float mx0 = s[0][0], mx1 = s[0][2];
#pragma unroll
            for (int nt = 0; nt < 8; nt++) {
                mx0 = fmaxf(mx0, fmaxf(s[nt][0], s[nt][1]));
                mx1 = fmaxf(mx1, fmaxf(s[nt][2], s[nt][3]));
            }
            mx0 = fmaxf(mx0, __shfl_xor_sync(0xffffffffu, mx0, 1));
            mx0 = fmaxf(mx0, __shfl_xor_sync(0xffffffffu, mx0, 2));
            mx1 = fmaxf(mx1, __shfl_xor_sync(0xffffffffu, mx1, 1));
            mx1 = fmaxf(mx1, __shfl_xor_sync(0xffffffffu, mx1, 2));
            const float mn0 = fmaxf(m0, mx0), mn1 = fmaxf(m1, mx1);
            const float f0 = __expf(m0 - mn0), f1 = __expf(m1 - mn1);
            float sum0 = 0.f, sum1 = 0.f;
#pragma unroll
            for (int nt = 0; nt < 8; nt++) {
                float p0 = __expf(s[nt][0] - mn0);
                float p1 = __expf(s[nt][1] - mn0);
                float p2 = __expf(s[nt][2] - mn1);
                float p3 = __expf(s[nt][3] - mn1);
                sum0 += p0 + p1; sum1 += p2 + p3;
                *(__half2*)&Ps[ph0 + nt * 8 + 2 * tig] = __floats2half2_rn(p0, p1);
                *(__half2*)&Ps[ph1 + nt * 8 + 2 * tig] = __floats2half2_rn(p2, p3);
#pragma unroll
                for (int e = 0; e < 2; e++) { o[nt][e] *= f0; o[nt][e + 2] *= f1; }
            }
            sum0 += __shfl_xor_sync(0xffffffffu, sum0, 1);
            sum0 += __shfl_xor_sync(0xffffffffu, sum0, 2);
            sum1 += __shfl_xor_sync(0xffffffffu, sum1, 1);
            sum1 += __shfl_xor_sync(0xffffffffu, sum1, 2);
            l0 = l0 * f0 + sum0;
            l1 = l1 * f1 + sum1;
            m0 = mn0; m1 = mn1;
            __syncwarp();

            // ---- O += P V (fp16 mma) ----
            const unsigned* Pw = (const unsigned*)Ps;
#pragma unroll
            for (int kc = 0; kc < 4; kc++) {
                unsigned a[4];
                a[0] = Pw[prw0 + kc * 8 + tig];
                a[1] = Pw[prw1 + kc * 8 + tig];
                a[2] = Pw[prw0 + kc * 8 + tig + 4];
                a[3] = Pw[prw1 + kc * 8 + tig + 4];
#pragma unroll
                for (int nt = 0; nt < 8; nt++) {
                    unsigned b0, b1;
                    ldsm_x2t(b0, b1, &Vs[st][(kc * 16 + (lane & 15)) * VSTRH + nt * 8]);
                    mma_f16(o[nt], a, b0, b1);
                }
            }
            st ^= 1;
        }

        // epilogue: write O as fp16 hi/lo split (consumed by proj GEMM)
        const float il0 = 1.f / l0, il1 = 1.f / l1;
#pragma unroll
        for (int nt = 0; nt < 8; nt++) {
            size_t c = h * D_ + nt * 8 + 2 * tig;
            size_t i0 = ((size_t)(b * N_ + r0)) * C_ + c;
            size_t i1 = ((size_t)(b * N_ + r0 + 8)) * C_ + c;
            float v0 = o[nt][0] * il0, v1 = o[nt][1] * il0;
            float v2 = o[nt][2] * il1, v3 = o[nt][3] * il1;
            __half h0 = __float2half_rn(v0), h1 = __float2half_rn(v1);
            __half h2 = __float2half_rn(v2), h3 = __float2half_rn(v3);
            *(__half2*)&g_atth[i0] = __halves2half2(h0, h1);
            *(__half2*)&g_atth[i1] = __halves2half2(h2, h3);
            *(__half2*)&g_attl[i0] = __halves2half2(
                __float2half_rn(v0 - __half2float(h0)), __float2half_rn(v1 - __half2float(h1)));
            *(__half2*)&g_attl[i1] = __halves2half2(
                __float2half_rn(v2 - __half2float(h2)), __float2half_rn(v3 - __half2float(h3)));
        }
    }
}

// ---------------------------------------------------------------------------
extern "C" void kernel_launch(void* const* d_in, const int* in_sizes, int n_in,
                              void* d_out, int out_size) {
    const float* x      = (const float*)d_in[0];   // [2,2048,1024]
    const float* w_qkv  = (const float*)d_in[1];   // [1024,3072]
    const float* w_proj = (const float*)d_in[2];   // [1024,1024]
    const float* b_proj = (const float*)d_in[3];   // [1024]
    float* out = (float*)d_out;                    // [2,2048,1024]

    float* qkv_ptr; cudaGetSymbolAddress((void**)&qkv_ptr, g_qkv);
    __half *xh, *xl, *wqh, *wql, *wph, *wpl, *ath, *atl;
    cudaGetSymbolAddress((void**)&xh,  g_xh);
    cudaGetSymbolAddress((void**)&xl,  g_xl);
    cudaGetSymbolAddress((void**)&wqh, g_wqh);
    cudaGetSymbolAddress((void**)&wql, g_wql);
    cudaGetSymbolAddress((void**)&wph, g_wph);
    cudaGetSymbolAddress((void**)&wpl, g_wpl);
    cudaGetSymbolAddress((void**)&ath, g_atth);
    cudaGetSymbolAddress((void**)&atl, g_attl);

    // 0) hi/lo fp16 splits of x, w_qkv, w_proj
    prep_split<<<(B_ * N_ * C_ / 4 + 255) / 256, 256>>>(x, xh, xl, B_ * N_ * C_ / 4);
    prep_split<<<(C_ * 3 * C_ / 4 + 255) / 256, 256>>>(w_qkv, wqh, wql, C_ * 3 * C_ / 4);
    prep_split<<<(C_ * C_ / 4 + 255) / 256, 256>>>(w_proj, wph, wpl, C_ * C_ / 4);

    // 1) QKV GEMM (fp16x3)
    {
        dim3 grid(3 * C_ / 128, (B_ * N_) / 128);
        gemm_f16x3<false><<<grid, 256>>>(xh, xl, wqh, wql, nullptr, qkv_ptr, B_ * N_, 3 * C_, C_);
    }
    // 2) V -> fp16 head-major
    conv_v<<<(B_ * N_ * (C_ / 4) + 255) / 256, 256>>>();
    // 3) amax -> scales
    {
        dim3 grid(8, 64);
        amax_part<<<grid, 256>>>();
        amax_fin<<<1, 64>>>();
    }
    // 4) fp8 quantize q,k
    quant_kernel<<<(B_ * N_ * 2 * (C_ / 4) + 255) / 256, 256>>>();
    // 5) tensor-core causal flash attention (cp.async pipelined K/V)
    {
        dim3 grid(N_ / 128, H_, B_);
        flash_fp8<<<grid, 128>>>();
    }
    // 6) output projection + bias (fp16x3)
    {
        dim3 grid(C_ / 128, (B_ * N_) / 128);
        gemm_f16x3<true><<<grid, 256>>>(ath, atl, wph, wpl, b_proj, out, B_ * N_, C_, C_);
    }
}

// round 14
// speedup vs baseline: 1.7183x; 1.0990x over previous
#include <cuda_runtime.h>
#include <cuda_fp16.h>
#include <cuda_fp8.h>
#include <math.h>

#define B_ 2
#define N_ 2048
#define C_ 1024
#define H_ 16
#define D_ 64

// Scratch (allocation-free contract: __device__ globals)
__device__ float g_qkv[B_ * N_ * 3 * C_];            // [B,N,3,H,D] as [B*N, 3C]
__device__ float g_scale[64];                        // 448/amax per (b,h,{q,k})
__device__ float g_iscale[64];                       // amax/448
__device__ float g_part[64 * 8];                     // partial amax
__device__ __align__(256) unsigned char g_q8[B_ * H_ * N_ * D_];  // fp8 q [b,h,n,d]
__device__ __align__(256) unsigned char g_k8[B_ * H_ * N_ * D_];  // fp8 k [b,h,n,d]
__device__ __align__(256) __half g_v16[B_ * H_ * N_ * D_];        // fp16 v [b,h,n,d]
// fp16 hi/lo splits
__device__ __half g_xh[B_ * N_ * C_];
__device__ __half g_xl[B_ * N_ * C_];
__device__ __half g_wqh[C_ * 3 * C_];
__device__ __half g_wql[C_ * 3 * C_];
__device__ __half g_wph[C_ * C_];
__device__ __half g_wpl[C_ * C_];
__device__ __half g_atth[B_ * N_ * C_];
__device__ __half g_attl[B_ * N_ * C_];

struct alignas(8) HH { __half2 a, b; };

// ---------------------------------------------------------------------------
// helpers
// ---------------------------------------------------------------------------
__device__ __forceinline__ void mma_f16(float* d, const unsigned* a, unsigned b0, unsigned b1) {
    asm volatile(
        "mma.sync.aligned.m16n8k16.row.col.f32.f16.f16.f32 "
        "{%0,%1,%2,%3},{%4,%5,%6,%7},{%8,%9},{%0,%1,%2,%3};"
        : "+f"(d[0]), "+f"(d[1]), "+f"(d[2]), "+f"(d[3])
        : "r"(a[0]), "r"(a[1]), "r"(a[2]), "r"(a[3]), "r"(b0), "r"(b1));
}

__device__ __forceinline__ void mma_e4m3(float* d, const unsigned* a, unsigned b0, unsigned b1) {
    asm volatile(
        "mma.sync.aligned.m16n8k32.row.col.f32.e4m3.e4m3.f32 "
        "{%0,%1,%2,%3},{%4,%5,%6,%7},{%8,%9},{%0,%1,%2,%3};"
        : "+f"(d[0]), "+f"(d[1]), "+f"(d[2]), "+f"(d[3])
        : "r"(a[0]), "r"(a[1]), "r"(a[2]), "r"(a[3]), "r"(b0), "r"(b1));
}

__device__ __forceinline__ void ldsm_x2t(unsigned& r0, unsigned& r1, const void* p) {
    unsigned s = (unsigned)__cvta_generic_to_shared(p);
    asm volatile("ldmatrix.sync.aligned.m8n8.x2.trans.shared.b16 {%0,%1}, [%2];"
                 : "=r"(r0), "=r"(r1) : "r"(s));
}

__device__ __forceinline__ void cp16(void* smem, const void* gmem) {
    unsigned s = (unsigned)__cvta_generic_to_shared(smem);
    asm volatile("cp.async.cg.shared.global [%0], [%1], 16;" :: "r"(s), "l"(gmem));
}
#define CP_COMMIT asm volatile("cp.async.commit_group;")
#define CP_WAIT0  asm volatile("cp.async.wait_group 0;")
#define CP_WAIT1  asm volatile("cp.async.wait_group 1;")

// ---------------------------------------------------------------------------
// fp32 -> fp16 hi/lo split (elementwise), vectorized by 4
// ---------------------------------------------------------------------------
__global__ void prep_split(const float* __restrict__ src, __half* __restrict__ hi,
                           __half* __restrict__ lo, int n4) {
    int i = blockIdx.x * blockDim.x + threadIdx.x;
    if (i >= n4) return;
    float4 v = ((const float4*)src)[i];
    __half h0 = __float2half_rn(v.x); float r0 = v.x - __half2float(h0);
    __half h1 = __float2half_rn(v.y); float r1 = v.y - __half2float(h1);
    __half h2 = __float2half_rn(v.z); float r2 = v.z - __half2float(h2);
    __half h3 = __float2half_rn(v.w); float r3 = v.w - __half2float(h3);
    HH hh; hh.a = __halves2half2(h0, h1); hh.b = __halves2half2(h2, h3);
    *(HH*)&hi[(size_t)i * 4] = hh;
    HH ll;
    ll.a = __halves2half2(__float2half_rn(r0), __float2half_rn(r1));
    ll.b = __halves2half2(__float2half_rn(r2), __float2half_rn(r3));
    *(HH*)&lo[(size_t)i * 4] = ll;
}

// ---------------------------------------------------------------------------
// fp16x3 GEMM (AhBh + AhBl + AlBh), 2-stage cp.async double buffer.
// Block 128x128, 8 warps (warp tile 32x64), K-step 32 (2 k16-substeps / sync).
// Dynamic smem (74 KB); __launch_bounds__(256,2) pins regs <= 128 -> 2 CTAs/SM.
// ---------------------------------------------------------------------------
#define ASTR 40              // A tile row stride (halfs): 32 + 8 pad
#define BSTR 136             // B tile row stride (halfs)
#define A_ST (128 * ASTR)    // 5120 halfs per stage (hi or lo)
#define B_ST (32 * BSTR)     // 4352 halfs per stage
#define GEMM_SMEM ((2 * A_ST * 2 + 2 * B_ST * 2) * 2)   // 75776 bytes

template <bool BIAS>
__global__ void __launch_bounds__(256, 2)
gemm_f16x3(const __half* __restrict__ Ahp, const __half* __restrict__ Alp,
           const __half* __restrict__ Bhp, const __half* __restrict__ Blp,
           const float* __restrict__ bias, float* __restrict__ Cm,
           int M, int N, int K) {
    extern __shared__ __half sm[];
    __half* As_h = sm;                       // [2][A_ST]
    __half* As_l = sm + 2 * A_ST;
    __half* Bs_h = sm + 4 * A_ST;            // [2][B_ST]
    __half* Bs_l = sm + 4 * A_ST + 2 * B_ST;

    const int bm = blockIdx.y * 128;
    const int bn = blockIdx.x * 128;
    const int tid = threadIdx.x;
    const int wid = tid >> 5, lane = tid & 31;
    const int gid = lane >> 2, tig = lane & 3;
    const int wm = (wid & 3) * 32;
    const int wn = (wid >> 2) * 64;
    const int lrow = lane & 15;

    float acc[2][8][4];
#pragma unroll
    for (int i = 0; i < 2; i++)
#pragma unroll
        for (int j = 0; j < 8; j++)
#pragma unroll
            for (int t = 0; t < 4; t++) acc[i][j][t] = 0.f;

    auto issue = [&](int kt, int buf) {
#pragma unroll
        for (int l = 0; l < 2; l++) {
            int id = tid + l * 256;
            int r = id >> 2, c8 = (id & 3) * 8;
            cp16(&As_h[buf * A_ST + r * ASTR + c8], &Ahp[(size_t)(bm + r) * K + kt + c8]);
            cp16(&As_l[buf * A_ST + r * ASTR + c8], &Alp[(size_t)(bm + r) * K + kt + c8]);
            int br_ = id >> 4, bc8 = (id & 15) * 8;
            cp16(&Bs_h[buf * B_ST + br_ * BSTR + bc8], &Bhp[(size_t)(kt + br_) * N + bn + bc8]);
            cp16(&Bs_l[buf * B_ST + br_ * BSTR + bc8], &Blp[(size_t)(kt + br_) * N + bn + bc8]);
        }
    };

    issue(0, 0);
    CP_COMMIT;
    CP_WAIT0;
    __syncthreads();

    int buf = 0;
    for (int kt = 0; kt < K; kt += 32) {
        if (kt + 32 < K) issue(kt + 32, buf ^ 1);
        CP_COMMIT;

        const unsigned* awh = (const unsigned*)(As_h + buf * A_ST);
        const unsigned* awl = (const unsigned*)(As_l + buf * A_ST);
        const __half* bsh = Bs_h + buf * B_ST;
        const __half* bsl = Bs_l + buf * B_ST;

#pragma unroll
        for (int ks = 0; ks < 2; ks++) {
            // A fragments (word stride ASTR/2 = 20; substep base ks*8 words)
            unsigned Af[2][4], Alf[2][4];
#pragma unroll
            for (int mt = 0; mt < 2; mt++) {
                int r0 = wm + mt * 16 + gid;
                int base = ks * 8 + tig;
                Af[mt][0]  = awh[r0 * 20 + base];
                Af[mt][1]  = awh[(r0 + 8) * 20 + base];
                Af[mt][2]  = awh[r0 * 20 + base + 4];
                Af[mt][3]  = awh[(r0 + 8) * 20 + base + 4];
                Alf[mt][0] = awl[r0 * 20 + base];
                Alf[mt][1] = awl[(r0 + 8) * 20 + base];
                Alf[mt][2] = awl[r0 * 20 + base + 4];
                Alf[mt][3] = awl[(r0 + 8) * 20 + base + 4];
            }
#pragma unroll
            for (int nt = 0; nt < 8; nt++) {
                unsigned bh0, bh1, bl0, bl1;
                ldsm_x2t(bh0, bh1, &bsh[(ks * 16 + lrow) * BSTR + wn + nt * 8]);
                ldsm_x2t(bl0, bl1, &bsl[(ks * 16 + lrow) * BSTR + wn + nt * 8]);
                // pass-interleaved: dependency chains spaced by 2
                mma_f16(acc[0][nt], Af[0],  bh0, bh1);
                mma_f16(acc[1][nt], Af[1],  bh0, bh1);
                mma_f16(acc[0][nt], Af[0],  bl0, bl1);
                mma_f16(acc[1][nt], Af[1],  bl0, bl1);
                mma_f16(acc[0][nt], Alf[0], bh0, bh1);
                mma_f16(acc[1][nt], Alf[1], bh0, bh1);
            }
        }
        CP_WAIT0;
        __syncthreads();
        buf ^= 1;
    }

#pragma unroll
    for (int mt = 0; mt < 2; mt++)
#pragma unroll
        for (int nt = 0; nt < 8; nt++) {
            int r = bm + wm + mt * 16 + gid;
            int c = bn + wn + nt * 8 + 2 * tig;
            float b0 = 0.f, b1 = 0.f;
            if (BIAS) { b0 = bias[c]; b1 = bias[c + 1]; }
            Cm[(size_t)r * N + c]           = acc[mt][nt][0] + b0;
            Cm[(size_t)r * N + c + 1]       = acc[mt][nt][1] + b1;
            Cm[(size_t)(r + 8) * N + c]     = acc[mt][nt][2] + b0;
            Cm[(size_t)(r + 8) * N + c + 1] = acc[mt][nt][3] + b1;
        }
}

// ---------------------------------------------------------------------------
// amax: two-stage
// ---------------------------------------------------------------------------
__global__ void amax_part() {
    const int part = blockIdx.x;
    const int bw = blockIdx.y;
    const int w = bw & 1;
    const int h = (bw >> 1) & 15;
    const int b = bw >> 5;
    __shared__ float red[256];
    float mx = 0.f;
    const int n0 = part * (N_ / 8);
    for (int i = threadIdx.x; i < (N_ / 8) * D_; i += 256) {
        int n = n0 + (i >> 6), d = i & 63;
        float v = g_qkv[((size_t)(b * N_ + n)) * (3 * C_) + w * C_ + h * D_ + d];
        mx = fmaxf(mx, fabsf(v));
    }
    red[threadIdx.x] = mx;
    __syncthreads();
    for (int s = 128; s; s >>= 1) {
        if (threadIdx.x < s) red[threadIdx.x] = fmaxf(red[threadIdx.x], red[threadIdx.x + s]);
        __syncthreads();
    }
    if (threadIdx.x == 0) g_part[bw * 8 + part] = red[0];
}

__global__ void amax_fin() {
    int bw = threadIdx.x;
    float mx = 0.f;
#pragma unroll
    for (int p = 0; p < 8; p++) mx = fmaxf(mx, g_part[bw * 8 + p]);
    float amax = fmaxf(mx, 1e-12f);
    g_scale[bw]  = 448.f / amax;
    g_iscale[bw] = amax / 448.f;
}

// ---------------------------------------------------------------------------
// fp8 quantize Q,K into head-major byte arrays
// ---------------------------------------------------------------------------
__global__ void quant_kernel() {
    int gid = blockIdx.x * blockDim.x + threadIdx.x;
    if (gid >= B_ * N_ * 2 * (C_ / 4)) return;
    int c4 = (gid & 255) * 4;
    int w  = (gid >> 8) & 1;
    int n  = (gid >> 9) & 2047;
    int b  = gid >> 20;
    int h  = c4 >> 6;
    int d  = c4 & 63;
    int si = (b * 16 + h) * 2 + w;
    float s = g_scale[si];
    size_t base = ((size_t)(b * N_ + n)) * (3 * C_) + w * C_ + c4;
    float4 v = *(const float4*)&g_qkv[base];
    unsigned u0 = __nv_cvt_float_to_fp8(v.x * s, __NV_SATFINITE, __NV_E4M3);
    unsigned u1 = __nv_cvt_float_to_fp8(v.y * s, __NV_SATFINITE, __NV_E4M3);
    unsigned u2 = __nv_cvt_float_to_fp8(v.z * s, __NV_SATFINITE, __NV_E4M3);
    unsigned u3 = __nv_cvt_float_to_fp8(v.w * s, __NV_SATFINITE, __NV_E4M3);
    unsigned word = u0 | (u1 << 8) | (u2 << 16) | (u3 << 24);
    unsigned char* dst = (w == 0) ? g_q8 : g_k8;
    *(unsigned*)&dst[((size_t)((b * 16 + h) * N_ + n)) * 64 + d] = word;
}

// ---------------------------------------------------------------------------
// V fp32 -> fp16 head-major (one-time conversion; flash loads halfs directly)
// ---------------------------------------------------------------------------
__global__ void conv_v() {
    int gid = blockIdx.x * blockDim.x + threadIdx.x;
    if (gid >= B_ * N_ * (C_ / 4)) return;
    int c4 = (gid & 255) * 4;
    int n  = (gid >> 8) & 2047;
    int b  = gid >> 19;
    int h  = c4 >> 6;
    int d  = c4 & 63;
    float4 v = *(const float4*)&g_qkv[((size_t)(b * N_ + n)) * (3 * C_) + 2 * C_ + c4];
    HH hh;
    hh.a = __floats2half2_rn(v.x, v.y);
    hh.b = __floats2half2_rn(v.z, v.w);
    *(HH*)&g_v16[((size_t)((b * 16 + h) * N_ + n)) * 64 + d] = hh;
}

// ---------------------------------------------------------------------------
// Tensor-core causal flash attention. QK^T fp8, PV fp16.
// cp.async double-buffered K8/V16 tiles; work-balanced pairs {p, 31-p}.
// ---------------------------------------------------------------------------
#define KSTR 20     // K8 tile row stride in words (80B, 16B-aligned, conflict-free)
#define VSTRH 72    // V tile row stride in halfs
#define PSTRH 72    // P tile row stride in halfs

__global__ void flash_fp8() {
    const int pid = blockIdx.x, h = blockIdx.y, b = blockIdx.z;
    __shared__ unsigned Ks8[2][64 * KSTR];
    __shared__ __half Vs[2][64 * VSTRH];
    __shared__ __half Ps[64 * PSTRH];

    const int tid = threadIdx.x;
    const int w = tid >> 5, lane = tid & 31;
    const int gid = lane >> 2, tig = lane & 3;
    const int bh = b * H_ + h;
    const unsigned* q8 = (const unsigned*)(g_q8 + (size_t)bh * N_ * D_);
    const unsigned* k8 = (const unsigned*)(g_k8 + (size_t)bh * N_ * D_);
    const __half* v16 = g_v16 + (size_t)bh * N_ * D_;
    const float sc = g_iscale[bh * 2 + 0] * g_iscale[bh * 2 + 1] * 0.125f;

    const int prw0 = (w * 16 + gid) * (PSTRH / 2);
    const int prw1 = (w * 16 + gid + 8) * (PSTRH / 2);
    const int ph0 = (w * 16 + gid) * PSTRH;
    const int ph1 = (w * 16 + gid + 8) * PSTRH;

    auto issue = [&](int kt_, int st) {
        const int k0 = kt_ * 64;
#pragma unroll
        for (int l = 0; l < 2; l++) {
            int idx = tid + l * 128;
            int rr = idx >> 2, cc = (idx & 3) * 4;
            cp16(&Ks8[st][rr * KSTR + cc], &k8[(size_t)(k0 + rr) * 16 + cc]);
        }
#pragma unroll
        for (int l = 0; l < 4; l++) {
            int idx = tid + l * 128;
            int rr = idx >> 3, ch = idx & 7;
            cp16(&Vs[st][rr * VSTRH + ch * 8], &v16[(size_t)(k0 + rr) * 64 + ch * 8]);
        }
    };

    for (int rep = 0; rep < 2; rep++) {
        const int qt = rep ? (N_ / 64 - 1 - pid) : pid;
        const int q0 = qt * 64;
        const int r0 = q0 + w * 16 + gid;

        unsigned qa[2][4];
#pragma unroll
        for (int ks = 0; ks < 2; ks++) {
            qa[ks][0] = q8[r0 * 16 + tig + 8 * ks];
            qa[ks][1] = q8[(r0 + 8) * 16 + tig + 8 * ks];
            qa[ks][2] = q8[r0 * 16 + tig + 4 + 8 * ks];
            qa[ks][3] = q8[(r0 + 8) * 16 + tig + 4 + 8 * ks];
        }

        float m0 = -INFINITY, m1 = -INFINITY, l0 = 0.f, l1 = 0.f;
        float o[8][4];
#pragma unroll
        for (int nt = 0; nt < 8; nt++)
#pragma unroll
            for (int e = 0; e < 4; e++) o[nt][e] = 0.f;

        __syncthreads();
        issue(0, 0);
        CP_COMMIT;

        int st = 0;
        for (int kt = 0; kt <= qt; kt++) {
            if (kt < qt) {
                __syncthreads();
                issue(kt + 1, st ^ 1);
                CP_COMMIT;
                CP_WAIT1;
            } else {
                CP_WAIT0;
            }
            __syncthreads();

            float s[8][4];
#pragma unroll
            for (int nt = 0; nt < 8; nt++) {
                s[nt][0] = s[nt][1] = s[nt][2] = s[nt][3] = 0.f;
                const int col = nt * 8 + gid;
                unsigned b0 = Ks8[st][col * KSTR + tig];
                unsigned b1 = Ks8[st][col * KSTR + tig + 4];
                mma_e4m3(s[nt], qa[0], b0, b1);
                unsigned b2 = Ks8[st][col * KSTR + tig + 8];
                unsigned b3 = Ks8[st][col * KSTR + tig + 12];
                mma_e4m3(s[nt], qa[1], b2, b3);
            }
            const bool diag = (kt == qt);
#pragma unroll
            for (int nt = 0; nt < 8; nt++) {
                s[nt][0] *= sc; s[nt][1] *= sc; s[nt][2] *= sc; s[nt][3] *= sc;
                if (diag) {
                    int cl = nt * 8 + 2 * tig;
                    int rl0 = w * 16 + gid, rl1 = rl0 + 8;
                    if (cl > rl0)     s[nt][0] = -1e30f;
                    if (cl + 1 > rl0) s[nt][1] = -1e30f;
                    if (cl > rl1)     s[nt][2] = -1e30f;
                    if (cl + 1 > rl1) s[nt][3] = -1e30f;
                }
            }
            float mx0 = s[0][0], mx1 = s[0][2];
#pragma unroll
            for (int nt = 0; nt < 8; nt++) {
                mx0 = fmaxf(mx0, fmaxf(s[nt][0], s[nt][1]));
                mx1 = fmaxf(mx1, fmaxf(s[nt][2], s[nt][3]));
            }
            mx0 = fmaxf(mx0, __shfl_xor_sync(0xffffffffu, mx0, 1));
            mx0 = fmaxf(mx0, __shfl_xor_sync(0xffffffffu, mx0, 2));
            mx1 = fmaxf(mx1, __shfl_xor_sync(0xffffffffu, mx1, 1));
            mx1 = fmaxf(mx1, __shfl_xor_sync(0xffffffffu, mx1, 2));
            const float mn0 = fmaxf(m0, mx0), mn1 = fmaxf(m1, mx1);
            const float f0 = __expf(m0 - mn0), f1 = __expf(m1 - mn1);
            float sum0 = 0.f, sum1 = 0.f;
#pragma unroll
            for (int nt = 0; nt < 8; nt++) {
                float p0 = __expf(s[nt][0] - mn0);
                float p1 = __expf(s[nt][1] - mn0);
                float p2 = __expf(s[nt][2] - mn1);
                float p3 = __expf(s[nt][3] - mn1);
                sum0 += p0 + p1; sum1 += p2 + p3;
                *(__half2*)&Ps[ph0 + nt * 8 + 2 * tig] = __floats2half2_rn(p0, p1);
                *(__half2*)&Ps[ph1 + nt * 8 + 2 * tig] = __floats2half2_rn(p2, p3);
#pragma unroll
                for (int e = 0; e < 2; e++) { o[nt][e] *= f0; o[nt][e + 2] *= f1; }
            }
            sum0 += __shfl_xor_sync(0xffffffffu, sum0, 1);
            sum0 += __shfl_xor_sync(0xffffffffu, sum0, 2);
            sum1 += __shfl_xor_sync(0xffffffffu, sum1, 1);
            sum1 += __shfl_xor_sync(0xffffffffu, sum1, 2);
            l0 = l0 * f0 + sum0;
            l1 = l1 * f1 + sum1;
            m0 = mn0; m1 = mn1;
            __syncwarp();

            const unsigned* Pw = (const unsigned*)Ps;
#pragma unroll
            for (int kc = 0; kc < 4; kc++) {
                unsigned a[4];
                a[0] = Pw[prw0 + kc * 8 + tig];
                a[1] = Pw[prw1 + kc * 8 + tig];
                a[2] = Pw[prw0 + kc * 8 + tig + 4];
                a[3] = Pw[prw1 + kc * 8 + tig + 4];
#pragma unroll
                for (int nt = 0; nt < 8; nt++) {
                    unsigned b0, b1;
                    ldsm_x2t(b0, b1, &Vs[st][(kc * 16 + (lane & 15)) * VSTRH + nt * 8]);
                    mma_f16(o[nt], a, b0, b1);
                }
            }
            st ^= 1;
        }

        const float il0 = 1.f / l0, il1 = 1.f / l1;
#pragma unroll
        for (int nt = 0; nt < 8; nt++) {
            size_t c = h * D_ + nt * 8 + 2 * tig;
            size_t i0 = ((size_t)(b * N_ + r0)) * C_ + c;
            size_t i1 = ((size_t)(b * N_ + r0 + 8)) * C_ + c;
            float v0 = o[nt][0] * il0, v1 = o[nt][1] * il0;
            float v2 = o[nt][2] * il1, v3 = o[nt][3] * il1;
            __half h0 = __float2half_rn(v0), h1 = __float2half_rn(v1);
            __half h2 = __float2half_rn(v2), h3 = __float2half_rn(v3);
            *(__half2*)&g_atth[i0] = __halves2half2(h0, h1);
            *(__half2*)&g_atth[i1] = __halves2half2(h2, h3);
            *(__half2*)&g_attl[i0] = __halves2half2(
                __float2half_rn(v0 - __half2float(h0)), __float2half_rn(v1 - __half2float(h1)));
            *(__half2*)&g_attl[i1] = __halves2half2(
                __float2half_rn(v2 - __half2float(h2)), __float2half_rn(v3 - __half2float(h3)));
        }
    }
}

// ---------------------------------------------------------------------------
extern "C" void kernel_launch(void* const* d_in, const int* in_sizes, int n_in,
                              void* d_out, int out_size) {
    const float* x      = (const float*)d_in[0];   // [2,2048,1024]
    const float* w_qkv  = (const float*)d_in[1];   // [1024,3072]
    const float* w_proj = (const float*)d_in[2];   // [1024,1024]
    const float* b_proj = (const float*)d_in[3];   // [1024]
    float* out = (float*)d_out;                    // [2,2048,1024]

    float* qkv_ptr; cudaGetSymbolAddress((void**)&qkv_ptr, g_qkv);
    __half *xh, *xl, *wqh, *wql, *wph, *wpl, *ath, *atl;
    cudaGetSymbolAddress((void**)&xh,  g_xh);
    cudaGetSymbolAddress((void**)&xl,  g_xl);
    cudaGetSymbolAddress((void**)&wqh, g_wqh);
    cudaGetSymbolAddress((void**)&wql, g_wql);
    cudaGetSymbolAddress((void**)&wph, g_wph);
    cudaGetSymbolAddress((void**)&wpl, g_wpl);
    cudaGetSymbolAddress((void**)&ath, g_atth);
    cudaGetSymbolAddress((void**)&atl, g_attl);

    // dynamic smem opt-in (idempotent; host attribute set, not an allocation)
    cudaFuncSetAttribute(gemm_f16x3<false>, cudaFuncAttributeMaxDynamicSharedMemorySize, GEMM_SMEM);
    cudaFuncSetAttribute(gemm_f16x3<true>,  cudaFuncAttributeMaxDynamicSharedMemorySize, GEMM_SMEM);

    // 0) hi/lo fp16 splits of x, w_qkv, w_proj
    prep_split<<<(B_ * N_ * C_ / 4 + 255) / 256, 256>>>(x, xh, xl, B_ * N_ * C_ / 4);
    prep_split<<<(C_ * 3 * C_ / 4 + 255) / 256, 256>>>(w_qkv, wqh, wql, C_ * 3 * C_ / 4);
    prep_split<<<(C_ * C_ / 4 + 255) / 256, 256>>>(w_proj, wph, wpl, C_ * C_ / 4);

    // 1) QKV GEMM (fp16x3, K-step 32)
    {
        dim3 grid(3 * C_ / 128, (B_ * N_) / 128);
        gemm_f16x3<false><<<grid, 256, GEMM_SMEM>>>(xh, xl, wqh, wql, nullptr, qkv_ptr,
                                                    B_ * N_, 3 * C_, C_);
    }
    // 2) V -> fp16 head-major
    conv_v<<<(B_ * N_ * (C_ / 4) + 255) / 256, 256>>>();
    // 3) amax -> scales
    {
        dim3 grid(8, 64);
        amax_part<<<grid, 256>>>();
        amax_fin<<<1, 64>>>();
    }
    // 4) fp8 quantize q,k
    quant_kernel<<<(B_ * N_ * 2 * (C_ / 4) + 255) / 256, 256>>>();
    // 5) tensor-core causal flash attention (cp.async pipelined K/V)
    {
        dim3 grid(N_ / 128, H_, B_);
        flash_fp8<<<grid, 128>>>();
    }
    // 6) output projection + bias (fp16x3, K-step 32)
    {
        dim3 grid(C_ / 128, (B_ * N_) / 128);
        gemm_f16x3<true><<<grid, 256, GEMM_SMEM>>>(ath, atl, wph, wpl, b_proj, out,
                                                   B_ * N_, C_, C_);
    }
}

// round 16
// speedup vs baseline: 1.8114x; 1.0541x over previous
#include <cuda_runtime.h>
#include <cuda_fp16.h>
#include <cuda_fp8.h>
#include <math.h>

#define B_ 2
#define N_ 2048
#define C_ 1024
#define H_ 16
#define D_ 64

// Scratch (allocation-free contract: __device__ globals)
__device__ float g_qkv[B_ * N_ * 3 * C_];            // [B,N,3,H,D] as [B*N, 3C]
__device__ float g_scale[64];                        // 448/amax per (b,h,{q,k})
__device__ float g_iscale[64];                       // amax/448
__device__ float g_part[64 * 8];                     // partial amax
__device__ __align__(256) unsigned char g_q8[B_ * H_ * N_ * D_];  // fp8 q [b,h,n,d]
__device__ __align__(256) unsigned char g_k8[B_ * H_ * N_ * D_];  // fp8 k [b,h,n,d]
__device__ __align__(256) __half g_v16[B_ * H_ * N_ * D_];        // fp16 v [b,h,n,d]
// fp16 splits: x hi+lo (QKV GEMM x3), weights hi+lo, att hi-only (proj x2)
__device__ __half g_xh[B_ * N_ * C_];
__device__ __half g_xl[B_ * N_ * C_];
__device__ __half g_wqh[C_ * 3 * C_];
__device__ __half g_wql[C_ * 3 * C_];
__device__ __half g_wph[C_ * C_];
__device__ __half g_wpl[C_ * C_];
__device__ __half g_atth[B_ * N_ * C_];

struct alignas(8) HH { __half2 a, b; };

// ---------------------------------------------------------------------------
// helpers
// ---------------------------------------------------------------------------
__device__ __forceinline__ void mma_f16(float* d, const unsigned* a, unsigned b0, unsigned b1) {
    asm volatile(
        "mma.sync.aligned.m16n8k16.row.col.f32.f16.f16.f32 "
        "{%0,%1,%2,%3},{%4,%5,%6,%7},{%8,%9},{%0,%1,%2,%3};"
        : "+f"(d[0]), "+f"(d[1]), "+f"(d[2]), "+f"(d[3])
        : "r"(a[0]), "r"(a[1]), "r"(a[2]), "r"(a[3]), "r"(b0), "r"(b1));
}

__device__ __forceinline__ void mma_e4m3(float* d, const unsigned* a, unsigned b0, unsigned b1) {
    asm volatile(
        "mma.sync.aligned.m16n8k32.row.col.f32.e4m3.e4m3.f32 "
        "{%0,%1,%2,%3},{%4,%5,%6,%7},{%8,%9},{%0,%1,%2,%3};"
        : "+f"(d[0]), "+f"(d[1]), "+f"(d[2]), "+f"(d[3])
        : "r"(a[0]), "r"(a[1]), "r"(a[2]), "r"(a[3]), "r"(b0), "r"(b1));
}

__device__ __forceinline__ void ldsm_x2t(unsigned& r0, unsigned& r1, const void* p) {
    unsigned s = (unsigned)__cvta_generic_to_shared(p);
    asm volatile("ldmatrix.sync.aligned.m8n8.x2.trans.shared.b16 {%0,%1}, [%2];"
                 : "=r"(r0), "=r"(r1) : "r"(s));
}

__device__ __forceinline__ void cp16(void* smem, const void* gmem) {
    unsigned s = (unsigned)__cvta_generic_to_shared(smem);
    asm volatile("cp.async.cg.shared.global [%0], [%1], 16;" :: "r"(s), "l"(gmem));
}
#define CP_COMMIT asm volatile("cp.async.commit_group;")
#define CP_WAIT0  asm volatile("cp.async.wait_group 0;")
#define CP_WAIT1  asm volatile("cp.async.wait_group 1;")

// ---------------------------------------------------------------------------
// fp32 -> fp16 splits
// ---------------------------------------------------------------------------
__global__ void prep_split(const float* __restrict__ src, __half* __restrict__ hi,
                           __half* __restrict__ lo, int n4) {
    int i = blockIdx.x * blockDim.x + threadIdx.x;
    if (i >= n4) return;
    float4 v = ((const float4*)src)[i];
    __half h0 = __float2half_rn(v.x); float r0 = v.x - __half2float(h0);
    __half h1 = __float2half_rn(v.y); float r1 = v.y - __half2float(h1);
    __half h2 = __float2half_rn(v.z); float r2 = v.z - __half2float(h2);
    __half h3 = __float2half_rn(v.w); float r3 = v.w - __half2float(h3);
    HH hh; hh.a = __halves2half2(h0, h1); hh.b = __halves2half2(h2, h3);
    *(HH*)&hi[(size_t)i * 4] = hh;
    HH ll;
    ll.a = __halves2half2(__float2half_rn(r0), __float2half_rn(r1));
    ll.b = __halves2half2(__float2half_rn(r2), __float2half_rn(r3));
    *(HH*)&lo[(size_t)i * 4] = ll;
}

// ---------------------------------------------------------------------------
// fp16x3 GEMM (AhBh + AhBl + AlBh): used for QKV (feeds fp8 quantizer; needs
// near-fp32 accuracy — fp8 boundary flips amplify any GEMM error ~16x).
// Block 128x128, 8 warps, K-step 32, 2-stage cp.async, dyn smem 74 KB.
// ---------------------------------------------------------------------------
#define ASTR 40              // A tile row stride (halfs)
#define BSTR 136             // B tile row stride (halfs)
#define A_ST (128 * ASTR)    // 5120 halfs per stage
#define B_ST (32 * BSTR)     // 4352 halfs per stage
#define GEMM3_SMEM ((2 * A_ST * 2 + 2 * B_ST * 2) * 2)   // 75776 bytes
#define GEMM2_SMEM ((2 * A_ST + 2 * B_ST * 2) * 2)       // 55296 bytes

__global__ void __launch_bounds__(256, 2)
gemm_f16x3(const __half* __restrict__ Ahp, const __half* __restrict__ Alp,
           const __half* __restrict__ Bhp, const __half* __restrict__ Blp,
           float* __restrict__ Cm, int M, int N, int K) {
    extern __shared__ __half sm[];
    __half* As_h = sm;                       // [2][A_ST]
    __half* As_l = sm + 2 * A_ST;
    __half* Bs_h = sm + 4 * A_ST;            // [2][B_ST]
    __half* Bs_l = sm + 4 * A_ST + 2 * B_ST;

    const int bm = blockIdx.y * 128;
    const int bn = blockIdx.x * 128;
    const int tid = threadIdx.x;
    const int wid = tid >> 5, lane = tid & 31;
    const int gid = lane >> 2, tig = lane & 3;
    const int wm = (wid & 3) * 32;
    const int wn = (wid >> 2) * 64;
    const int lrow = lane & 15;

    float acc[2][8][4];
#pragma unroll
    for (int i = 0; i < 2; i++)
#pragma unroll
        for (int j = 0; j < 8; j++)
#pragma unroll
            for (int t = 0; t < 4; t++) acc[i][j][t] = 0.f;

    auto issue = [&](int kt, int buf) {
#pragma unroll
        for (int l = 0; l < 2; l++) {
            int id = tid + l * 256;
            int r = id >> 2, c8 = (id & 3) * 8;
            cp16(&As_h[buf * A_ST + r * ASTR + c8], &Ahp[(size_t)(bm + r) * K + kt + c8]);
            cp16(&As_l[buf * A_ST + r * ASTR + c8], &Alp[(size_t)(bm + r) * K + kt + c8]);
            int br_ = id >> 4, bc8 = (id & 15) * 8;
            cp16(&Bs_h[buf * B_ST + br_ * BSTR + bc8], &Bhp[(size_t)(kt + br_) * N + bn + bc8]);
            cp16(&Bs_l[buf * B_ST + br_ * BSTR + bc8], &Blp[(size_t)(kt + br_) * N + bn + bc8]);
        }
    };

    issue(0, 0);
    CP_COMMIT;
    CP_WAIT0;
    __syncthreads();

    int buf = 0;
    for (int kt = 0; kt < K; kt += 32) {
        if (kt + 32 < K) issue(kt + 32, buf ^ 1);
        CP_COMMIT;

        const unsigned* awh = (const unsigned*)(As_h + buf * A_ST);
        const unsigned* awl = (const unsigned*)(As_l + buf * A_ST);
        const __half* bsh = Bs_h + buf * B_ST;
        const __half* bsl = Bs_l + buf * B_ST;

#pragma unroll
        for (int ks = 0; ks < 2; ks++) {
            unsigned Af[2][4], Alf[2][4];
#pragma unroll
            for (int mt = 0; mt < 2; mt++) {
                int r0 = wm + mt * 16 + gid;
                int base = ks * 8 + tig;
                Af[mt][0]  = awh[r0 * 20 + base];
                Af[mt][1]  = awh[(r0 + 8) * 20 + base];
                Af[mt][2]  = awh[r0 * 20 + base + 4];
                Af[mt][3]  = awh[(r0 + 8) * 20 + base + 4];
                Alf[mt][0] = awl[r0 * 20 + base];
                Alf[mt][1] = awl[(r0 + 8) * 20 + base];
                Alf[mt][2] = awl[r0 * 20 + base + 4];
                Alf[mt][3] = awl[(r0 + 8) * 20 + base + 4];
            }
#pragma unroll
            for (int nt = 0; nt < 8; nt++) {
                unsigned bh0, bh1, bl0, bl1;
                ldsm_x2t(bh0, bh1, &bsh[(ks * 16 + lrow) * BSTR + wn + nt * 8]);
                ldsm_x2t(bl0, bl1, &bsl[(ks * 16 + lrow) * BSTR + wn + nt * 8]);
                mma_f16(acc[0][nt], Af[0],  bh0, bh1);
                mma_f16(acc[1][nt], Af[1],  bh0, bh1);
                mma_f16(acc[0][nt], Af[0],  bl0, bl1);
                mma_f16(acc[1][nt], Af[1],  bl0, bl1);
                mma_f16(acc[0][nt], Alf[0], bh0, bh1);
                mma_f16(acc[1][nt], Alf[1], bh0, bh1);
            }
        }
        CP_WAIT0;
        __syncthreads();
        buf ^= 1;
    }

#pragma unroll
    for (int mt = 0; mt < 2; mt++)
#pragma unroll
        for (int nt = 0; nt < 8; nt++) {
            int r = bm + wm + mt * 16 + gid;
            int c = bn + wn + nt * 8 + 2 * tig;
            Cm[(size_t)r * N + c]           = acc[mt][nt][0];
            Cm[(size_t)r * N + c + 1]       = acc[mt][nt][1];
            Cm[(size_t)(r + 8) * N + c]     = acc[mt][nt][2];
            Cm[(size_t)(r + 8) * N + c + 1] = acc[mt][nt][3];
        }
}

// ---------------------------------------------------------------------------
// fp16x2 GEMM (Ah(Bh+Bl), +bias): proj only — downstream of all quantizers,
// where the dropped AlBh term costs only ~2.4e-4 relative.
// ---------------------------------------------------------------------------
__global__ void __launch_bounds__(256, 2)
gemm_f16x2(const __half* __restrict__ Ahp,
           const __half* __restrict__ Bhp, const __half* __restrict__ Blp,
           const float* __restrict__ bias, float* __restrict__ Cm,
           int M, int N, int K) {
    extern __shared__ __half sm[];
    __half* As   = sm;                       // [2][A_ST]
    __half* Bs_h = sm + 2 * A_ST;            // [2][B_ST]
    __half* Bs_l = sm + 2 * A_ST + 2 * B_ST;

    const int bm = blockIdx.y * 128;
    const int bn = blockIdx.x * 128;
    const int tid = threadIdx.x;
    const int wid = tid >> 5, lane = tid & 31;
    const int gid = lane >> 2, tig = lane & 3;
    const int wm = (wid & 3) * 32;
    const int wn = (wid >> 2) * 64;
    const int lrow = lane & 15;

    float acc[2][8][4];
#pragma unroll
    for (int i = 0; i < 2; i++)
#pragma unroll
        for (int j = 0; j < 8; j++)
#pragma unroll
            for (int t = 0; t < 4; t++) acc[i][j][t] = 0.f;

    auto issue = [&](int kt, int buf) {
#pragma unroll
        for (int l = 0; l < 2; l++) {
            int id = tid + l * 256;
            int r = id >> 2, c8 = (id & 3) * 8;
            cp16(&As[buf * A_ST + r * ASTR + c8], &Ahp[(size_t)(bm + r) * K + kt + c8]);
            int br_ = id >> 4, bc8 = (id & 15) * 8;
            cp16(&Bs_h[buf * B_ST + br_ * BSTR + bc8], &Bhp[(size_t)(kt + br_) * N + bn + bc8]);
            cp16(&Bs_l[buf * B_ST + br_ * BSTR + bc8], &Blp[(size_t)(kt + br_) * N + bn + bc8]);
        }
    };

    issue(0, 0);
    CP_COMMIT;
    CP_WAIT0;
    __syncthreads();

    int buf = 0;
    for (int kt = 0; kt < K; kt += 32) {
        if (kt + 32 < K) issue(kt + 32, buf ^ 1);
        CP_COMMIT;

        const unsigned* aw = (const unsigned*)(As + buf * A_ST);
        const __half* bsh = Bs_h + buf * B_ST;
        const __half* bsl = Bs_l + buf * B_ST;

#pragma unroll
        for (int ks = 0; ks < 2; ks++) {
            unsigned Af[2][4];
#pragma unroll
            for (int mt = 0; mt < 2; mt++) {
                int r0 = wm + mt * 16 + gid;
                int base = ks * 8 + tig;
                Af[mt][0] = aw[r0 * 20 + base];
                Af[mt][1] = aw[(r0 + 8) * 20 + base];
                Af[mt][2] = aw[r0 * 20 + base + 4];
                Af[mt][3] = aw[(r0 + 8) * 20 + base + 4];
            }
#pragma unroll
            for (int nt = 0; nt < 8; nt++) {
                unsigned bh0, bh1, bl0, bl1;
                ldsm_x2t(bh0, bh1, &bsh[(ks * 16 + lrow) * BSTR + wn + nt * 8]);
                ldsm_x2t(bl0, bl1, &bsl[(ks * 16 + lrow) * BSTR + wn + nt * 8]);
                mma_f16(acc[0][nt], Af[0], bh0, bh1);
                mma_f16(acc[1][nt], Af[1], bh0, bh1);
                mma_f16(acc[0][nt], Af[0], bl0, bl1);
                mma_f16(acc[1][nt], Af[1], bl0, bl1);
            }
        }
        CP_WAIT0;
        __syncthreads();
        buf ^= 1;
    }

#pragma unroll
    for (int mt = 0; mt < 2; mt++)
#pragma unroll
        for (int nt = 0; nt < 8; nt++) {
            int r = bm + wm + mt * 16 + gid;
            int c = bn + wn + nt * 8 + 2 * tig;
            float b0 = bias[c], b1 = bias[c + 1];
            Cm[(size_t)r * N + c]           = acc[mt][nt][0] + b0;
            Cm[(size_t)r * N + c + 1]       = acc[mt][nt][1] + b1;
            Cm[(size_t)(r + 8) * N + c]     = acc[mt][nt][2] + b0;
            Cm[(size_t)(r + 8) * N + c + 1] = acc[mt][nt][3] + b1;
        }
}

// ---------------------------------------------------------------------------
// amax: two-stage
// ---------------------------------------------------------------------------
__global__ void amax_part() {
    const int part = blockIdx.x;
    const int bw = blockIdx.y;
    const int w = bw & 1;
    const int h = (bw >> 1) & 15;
    const int b = bw >> 5;
    __shared__ float red[256];
    float mx = 0.f;
    const int n0 = part * (N_ / 8);
    for (int i = threadIdx.x; i < (N_ / 8) * D_; i += 256) {
        int n = n0 + (i >> 6), d = i & 63;
        float v = g_qkv[((size_t)(b * N_ + n)) * (3 * C_) + w * C_ + h * D_ + d];
        mx = fmaxf(mx, fabsf(v));
    }
    red[threadIdx.x] = mx;
    __syncthreads();
    for (int s = 128; s; s >>= 1) {
        if (threadIdx.x < s) red[threadIdx.x] = fmaxf(red[threadIdx.x], red[threadIdx.x + s]);
        __syncthreads();
    }
    if (threadIdx.x == 0) g_part[bw * 8 + part] = red[0];
}

__global__ void amax_fin() {
    int bw = threadIdx.x;
    float mx = 0.f;
#pragma unroll
    for (int p = 0; p < 8; p++) mx = fmaxf(mx, g_part[bw * 8 + p]);
    float amax = fmaxf(mx, 1e-12f);
    g_scale[bw]  = 448.f / amax;
    g_iscale[bw] = amax / 448.f;
}

// ---------------------------------------------------------------------------
// fp8 quantize Q,K into head-major byte arrays
// ---------------------------------------------------------------------------
__global__ void quant_kernel() {
    int gid = blockIdx.x * blockDim.x + threadIdx.x;
    if (gid >= B_ * N_ * 2 * (C_ / 4)) return;
    int c4 = (gid & 255) * 4;
    int w  = (gid >> 8) & 1;
    int n  = (gid >> 9) & 2047;
    int b  = gid >> 20;
    int h  = c4 >> 6;
    int d  = c4 & 63;
    int si = (b * 16 + h) * 2 + w;
    float s = g_scale[si];
    size_t base = ((size_t)(b * N_ + n)) * (3 * C_) + w * C_ + c4;
    float4 v = *(const float4*)&g_qkv[base];
    unsigned u0 = __nv_cvt_float_to_fp8(v.x * s, __NV_SATFINITE, __NV_E4M3);
    unsigned u1 = __nv_cvt_float_to_fp8(v.y * s, __NV_SATFINITE, __NV_E4M3);
    unsigned u2 = __nv_cvt_float_to_fp8(v.z * s, __NV_SATFINITE, __NV_E4M3);
    unsigned u3 = __nv_cvt_float_to_fp8(v.w * s, __NV_SATFINITE, __NV_E4M3);
    unsigned word = u0 | (u1 << 8) | (u2 << 16) | (u3 << 24);
    unsigned char* dst = (w == 0) ? g_q8 : g_k8;
    *(unsigned*)&dst[((size_t)((b * 16 + h) * N_ + n)) * 64 + d] = word;
}

// ---------------------------------------------------------------------------
// V fp32 -> fp16 head-major
// ---------------------------------------------------------------------------
__global__ void conv_v() {
    int gid = blockIdx.x * blockDim.x + threadIdx.x;
    if (gid >= B_ * N_ * (C_ / 4)) return;
    int c4 = (gid & 255) * 4;
    int n  = (gid >> 8) & 2047;
    int b  = gid >> 19;
    int h  = c4 >> 6;
    int d  = c4 & 63;
    float4 v = *(const float4*)&g_qkv[((size_t)(b * N_ + n)) * (3 * C_) + 2 * C_ + c4];
    HH hh;
    hh.a = __floats2half2_rn(v.x, v.y);
    hh.b = __floats2half2_rn(v.z, v.w);
    *(HH*)&g_v16[((size_t)((b * 16 + h) * N_ + n)) * 64 + d] = hh;
}

// ---------------------------------------------------------------------------
// Tensor-core causal flash attention. QK^T fp8, PV fp16.
// cp.async double-buffered K8/V16 tiles; work-balanced pairs {p, 31-p}.
// Epilogue writes fp16 hi only (proj x2 A operand).
// ---------------------------------------------------------------------------
#define KSTR 20     // K8 tile row stride in words
#define VSTRH 72    // V tile row stride in halfs
#define PSTRH 72    // P tile row stride in halfs

__global__ void flash_fp8() {
    const int pid = blockIdx.x, h = blockIdx.y, b = blockIdx.z;
    __shared__ unsigned Ks8[2][64 * KSTR];
    __shared__ __half Vs[2][64 * VSTRH];
    __shared__ __half Ps[64 * PSTRH];

    const int tid = threadIdx.x;
    const int w = tid >> 5, lane = tid & 31;
    const int gid = lane >> 2, tig = lane & 3;
    const int bh = b * H_ + h;
    const unsigned* q8 = (const unsigned*)(g_q8 + (size_t)bh * N_ * D_);
    const unsigned* k8 = (const unsigned*)(g_k8 + (size_t)bh * N_ * D_);
    const __half* v16 = g_v16 + (size_t)bh * N_ * D_;
    const float sc = g_iscale[bh * 2 + 0] * g_iscale[bh * 2 + 1] * 0.125f;

    const int prw0 = (w * 16 + gid) * (PSTRH / 2);
    const int prw1 = (w * 16 + gid + 8) * (PSTRH / 2);
    const int ph0 = (w * 16 + gid) * PSTRH;
    const int ph1 = (w * 16 + gid + 8) * PSTRH;

    auto issue = [&](int kt_, int st) {
        const int k0 = kt_ * 64;
#pragma unroll
        for (int l = 0; l < 2; l++) {
            int idx = tid + l * 128;
            int rr = idx >> 2, cc = (idx & 3) * 4;
            cp16(&Ks8[st][rr * KSTR + cc], &k8[(size_t)(k0 + rr) * 16 + cc]);
        }
#pragma unroll
        for (int l = 0; l < 4; l++) {
            int idx = tid + l * 128;
            int rr = idx >> 3, ch = idx & 7;
            cp16(&Vs[st][rr * VSTRH + ch * 8], &v16[(size_t)(k0 + rr) * 64 + ch * 8]);
        }
    };

    for (int rep = 0; rep < 2; rep++) {
        const int qt = rep ? (N_ / 64 - 1 - pid) : pid;
        const int q0 = qt * 64;
        const int r0 = q0 + w * 16 + gid;

        unsigned qa[2][4];
#pragma unroll
        for (int ks = 0; ks < 2; ks++) {
            qa[ks][0] = q8[r0 * 16 + tig + 8 * ks];
            qa[ks][1] = q8[(r0 + 8) * 16 + tig + 8 * ks];
            qa[ks][2] = q8[r0 * 16 + tig + 4 + 8 * ks];
            qa[ks][3] = q8[(r0 + 8) * 16 + tig + 4 + 8 * ks];
        }

        float m0 = -INFINITY, m1 = -INFINITY, l0 = 0.f, l1 = 0.f;
        float o[8][4];
#pragma unroll
        for (int nt = 0; nt < 8; nt++)
#pragma unroll
            for (int e = 0; e < 4; e++) o[nt][e] = 0.f;

        __syncthreads();
        issue(0, 0);
        CP_COMMIT;

        int st = 0;
        for (int kt = 0; kt <= qt; kt++) {
            if (kt < qt) {
                __syncthreads();
                issue(kt + 1, st ^ 1);
                CP_COMMIT;
                CP_WAIT1;
            } else {
                CP_WAIT0;
            }
            __syncthreads();

            float s[8][4];
#pragma unroll
            for (int nt = 0; nt < 8; nt++) {
                s[nt][0] = s[nt][1] = s[nt][2] = s[nt][3] = 0.f;
                const int col = nt * 8 + gid;
                unsigned b0 = Ks8[st][col * KSTR + tig];
                unsigned b1 = Ks8[st][col * KSTR + tig + 4];
                mma_e4m3(s[nt], qa[0], b0, b1);
                unsigned b2 = Ks8[st][col * KSTR + tig + 8];
                unsigned b3 = Ks8[st][col * KSTR + tig + 12];
                mma_e4m3(s[nt], qa[1], b2, b3);
            }
            const bool diag = (kt == qt);
#pragma unroll
            for (int nt = 0; nt < 8; nt++) {
                s[nt][0] *= sc; s[nt][1] *= sc; s[nt][2] *= sc; s[nt][3] *= sc;
                if (diag) {
                    int cl = nt * 8 + 2 * tig;
                    int rl0 = w * 16 + gid, rl1 = rl0 + 8;
                    if (cl > rl0)     s[nt][0] = -1e30f;
                    if (cl + 1 > rl0) s[nt][1] = -1e30f;
                    if (cl > rl1)     s[nt][2] = -1e30f;
                    if (cl + 1 > rl1) s[nt][3] = -1e30f;
                }
            }
            float mx0 = s[0][0], mx1 = s[0][2];
#pragma unroll
            for (int nt = 0; nt < 8; nt++) {
                mx0 = fmaxf(mx0, fmaxf(s[nt][0], s[nt][1]));
                mx1 = fmaxf(mx1, fmaxf(s[nt][2], s[nt][3]));
            }
            mx0 = fmaxf(mx0, __shfl_xor_sync(0xffffffffu, mx0, 1));
            mx0 = fmaxf(mx0, __shfl_xor_sync(0xffffffffu, mx0, 2));
            mx1 = fmaxf(mx1, __shfl_xor_sync(0xffffffffu, mx1, 1));
            mx1 = fmaxf(mx1, __shfl_xor_sync(0xffffffffu, mx1, 2));
            const float mn0 = fmaxf(m0, mx0), mn1 = fmaxf(m1, mx1);
            const float f0 = __expf(m0 - mn0), f1 = __expf(m1 - mn1);
            float sum0 = 0.f, sum1 = 0.f;
#pragma unroll
            for (int nt = 0; nt < 8; nt++) {
                float p0 = __expf(s[nt][0] - mn0);
                float p1 = __expf(s[nt][1] - mn0);
                float p2 = __expf(s[nt][2] - mn1);
                float p3 = __expf(s[nt][3] - mn1);
                sum0 += p0 + p1; sum1 += p2 + p3;
                *(__half2*)&Ps[ph0 + nt * 8 + 2 * tig] = __floats2half2_rn(p0, p1);
                *(__half2*)&Ps[ph1 + nt * 8 + 2 * tig] = __floats2half2_rn(p2, p3);
#pragma unroll
                for (int e = 0; e < 2; e++) { o[nt][e] *= f0; o[nt][e + 2] *= f1; }
            }
            sum0 += __shfl_xor_sync(0xffffffffu, sum0, 1);
            sum0 += __shfl_xor_sync(0xffffffffu, sum0, 2);
            sum1 += __shfl_xor_sync(0xffffffffu, sum1, 1);
            sum1 += __shfl_xor_sync(0xffffffffu, sum1, 2);
            l0 = l0 * f0 + sum0;
            l1 = l1 * f1 + sum1;
            m0 = mn0; m1 = mn1;
            __syncwarp();

            const unsigned* Pw = (const unsigned*)Ps;
#pragma unroll
            for (int kc = 0; kc < 4; kc++) {
                unsigned a[4];
                a[0] = Pw[prw0 + kc * 8 + tig];
                a[1] = Pw[prw1 + kc * 8 + tig];
                a[2] = Pw[prw0 + kc * 8 + tig + 4];
                a[3] = Pw[prw1 + kc * 8 + tig + 4];
#pragma unroll
                for (int nt = 0; nt < 8; nt++) {
                    unsigned b0, b1;
                    ldsm_x2t(b0, b1, &Vs[st][(kc * 16 + (lane & 15)) * VSTRH + nt * 8]);
                    mma_f16(o[nt], a, b0, b1);
                }
            }
            st ^= 1;
        }

        // epilogue: write O as fp16 hi only
        const float il0 = 1.f / l0, il1 = 1.f / l1;
#pragma unroll
        for (int nt = 0; nt < 8; nt++) {
            size_t c = h * D_ + nt * 8 + 2 * tig;
            size_t i0 = ((size_t)(b * N_ + r0)) * C_ + c;
            size_t i1 = ((size_t)(b * N_ + r0 + 8)) * C_ + c;
            *(__half2*)&g_atth[i0] = __floats2half2_rn(o[nt][0] * il0, o[nt][1] * il0);
            *(__half2*)&g_atth[i1] = __floats2half2_rn(o[nt][2] * il1, o[nt][3] * il1);
        }
    }
}

// ---------------------------------------------------------------------------
extern "C" void kernel_launch(void* const* d_in, const int* in_sizes, int n_in,
                              void* d_out, int out_size) {
    const float* x      = (const float*)d_in[0];   // [2,2048,1024]
    const float* w_qkv  = (const float*)d_in[1];   // [1024,3072]
    const float* w_proj = (const float*)d_in[2];   // [1024,1024]
    const float* b_proj = (const float*)d_in[3];   // [1024]
    float* out = (float*)d_out;                    // [2,2048,1024]

    float* qkv_ptr; cudaGetSymbolAddress((void**)&qkv_ptr, g_qkv);
    __half *xh, *xl, *wqh, *wql, *wph, *wpl, *ath;
    cudaGetSymbolAddress((void**)&xh,  g_xh);
    cudaGetSymbolAddress((void**)&xl,  g_xl);
    cudaGetSymbolAddress((void**)&wqh, g_wqh);
    cudaGetSymbolAddress((void**)&wql, g_wql);
    cudaGetSymbolAddress((void**)&wph, g_wph);
    cudaGetSymbolAddress((void**)&wpl, g_wpl);
    cudaGetSymbolAddress((void**)&ath, g_atth);

    // dynamic smem opt-in (idempotent host attribute set)
    cudaFuncSetAttribute(gemm_f16x3, cudaFuncAttributeMaxDynamicSharedMemorySize, GEMM3_SMEM);
    cudaFuncSetAttribute(gemm_f16x2, cudaFuncAttributeMaxDynamicSharedMemorySize, GEMM2_SMEM);

    // 0) fp16 splits: x hi+lo (QKV x3), weights hi+lo
    prep_split<<<(B_ * N_ * C_ / 4 + 255) / 256, 256>>>(x, xh, xl, B_ * N_ * C_ / 4);
    prep_split<<<(C_ * 3 * C_ / 4 + 255) / 256, 256>>>(w_qkv, wqh, wql, C_ * 3 * C_ / 4);
    prep_split<<<(C_ * C_ / 4 + 255) / 256, 256>>>(w_proj, wph, wpl, C_ * C_ / 4);

    // 1) QKV GEMM (fp16x3 — feeds fp8 quantizer, needs full accuracy)
    {
        dim3 grid(3 * C_ / 128, (B_ * N_) / 128);
        gemm_f16x3<<<grid, 256, GEMM3_SMEM>>>(xh, xl, wqh, wql, qkv_ptr, B_ * N_, 3 * C_, C_);
    }
    // 2) V -> fp16 head-major
    conv_v<<<(B_ * N_ * (C_ / 4) + 255) / 256, 256>>>();
    // 3) amax -> scales
    {
        dim3 grid(8, 64);
        amax_part<<<grid, 256>>>();
        amax_fin<<<1, 64>>>();
    }
    // 4) fp8 quantize q,k
    quant_kernel<<<(B_ * N_ * 2 * (C_ / 4) + 255) / 256, 256>>>();
    // 5) tensor-core causal flash attention
    {
        dim3 grid(N_ / 128, H_, B_);
        flash_fp8<<<grid, 128>>>();
    }
    // 6) output projection + bias (fp16x2 — downstream of all quantizers)
    {
        dim3 grid(C_ / 128, (B_ * N_) / 128);
        gemm_f16x2<<<grid, 256, GEMM2_SMEM>>>(ath, wph, wpl, b_proj, out, B_ * N_, C_, C_);
    }
}

// round 17
// speedup vs baseline: 1.9119x; 1.0555x over previous
#include <cuda_runtime.h>
#include <cuda_fp16.h>
#include <cuda_fp8.h>
#include <math.h>

#define B_ 2
#define N_ 2048
#define C_ 1024
#define H_ 16
#define D_ 64

// Scratch (allocation-free contract: __device__ globals)
__device__ float g_qkv[B_ * N_ * 3 * C_];            // [B,N,3C]; only q,k thirds used
__device__ float g_scale[64];                        // 448/amax per (b,h,{q,k})
__device__ float g_iscale[64];                       // amax/448
__device__ float g_part[64 * 8];                     // partial amax
__device__ __align__(256) unsigned char g_q8[B_ * H_ * N_ * D_];  // fp8 q [b,h,n,d]
__device__ __align__(256) unsigned char g_k8[B_ * H_ * N_ * D_];  // fp8 k [b,h,n,d]
__device__ __align__(256) __half g_v16[B_ * H_ * N_ * D_];        // fp16 v [b,h,n,d]
// fp16 splits
__device__ __half g_xh[B_ * N_ * C_];
__device__ __half g_xl[B_ * N_ * C_];
__device__ __half g_wqh[C_ * 3 * C_];
__device__ __half g_wql[C_ * 3 * C_];
__device__ __half g_wph[C_ * C_];
__device__ __half g_wpl[C_ * C_];
__device__ __half g_atth[B_ * N_ * C_];

struct alignas(8) HH { __half2 a, b; };

// ---------------------------------------------------------------------------
// helpers
// ---------------------------------------------------------------------------
__device__ __forceinline__ void mma_f16(float* d, const unsigned* a, unsigned b0, unsigned b1) {
    asm volatile(
        "mma.sync.aligned.m16n8k16.row.col.f32.f16.f16.f32 "
        "{%0,%1,%2,%3},{%4,%5,%6,%7},{%8,%9},{%0,%1,%2,%3};"
        : "+f"(d[0]), "+f"(d[1]), "+f"(d[2]), "+f"(d[3])
        : "r"(a[0]), "r"(a[1]), "r"(a[2]), "r"(a[3]), "r"(b0), "r"(b1));
}

__device__ __forceinline__ void mma_e4m3(float* d, const unsigned* a, unsigned b0, unsigned b1) {
    asm volatile(
        "mma.sync.aligned.m16n8k32.row.col.f32.e4m3.e4m3.f32 "
        "{%0,%1,%2,%3},{%4,%5,%6,%7},{%8,%9},{%0,%1,%2,%3};"
        : "+f"(d[0]), "+f"(d[1]), "+f"(d[2]), "+f"(d[3])
        : "r"(a[0]), "r"(a[1]), "r"(a[2]), "r"(a[3]), "r"(b0), "r"(b1));
}

__device__ __forceinline__ void ldsm_x2t(unsigned& r0, unsigned& r1, const void* p) {
    unsigned s = (unsigned)__cvta_generic_to_shared(p);
    asm volatile("ldmatrix.sync.aligned.m8n8.x2.trans.shared.b16 {%0,%1}, [%2];"
                 : "=r"(r0), "=r"(r1) : "r"(s));
}

__device__ __forceinline__ void cp16(void* smem, const void* gmem) {
    unsigned s = (unsigned)__cvta_generic_to_shared(smem);
    asm volatile("cp.async.cg.shared.global [%0], [%1], 16;" :: "r"(s), "l"(gmem));
}
#define CP_COMMIT asm volatile("cp.async.commit_group;")
#define CP_WAIT0  asm volatile("cp.async.wait_group 0;")
#define CP_WAIT1  asm volatile("cp.async.wait_group 1;")

// ---------------------------------------------------------------------------
// fp32 -> fp16 splits
// ---------------------------------------------------------------------------
__global__ void prep_split(const float* __restrict__ src, __half* __restrict__ hi,
                           __half* __restrict__ lo, int n4) {
    int i = blockIdx.x * blockDim.x + threadIdx.x;
    if (i >= n4) return;
    float4 v = ((const float4*)src)[i];
    __half h0 = __float2half_rn(v.x); float r0 = v.x - __half2float(h0);
    __half h1 = __float2half_rn(v.y); float r1 = v.y - __half2float(h1);
    __half h2 = __float2half_rn(v.z); float r2 = v.z - __half2float(h2);
    __half h3 = __float2half_rn(v.w); float r3 = v.w - __half2float(h3);
    HH hh; hh.a = __halves2half2(h0, h1); hh.b = __halves2half2(h2, h3);
    *(HH*)&hi[(size_t)i * 4] = hh;
    HH ll;
    ll.a = __halves2half2(__float2half_rn(r0), __float2half_rn(r1));
    ll.b = __halves2half2(__float2half_rn(r2), __float2half_rn(r3));
    *(HH*)&lo[(size_t)i * 4] = ll;
}

// ---------------------------------------------------------------------------
// Tiling constants shared by GEMM kernels. Block 128x128, 8 warps, K-step 32.
// ---------------------------------------------------------------------------
#define ASTR 40              // A tile row stride (halfs)
#define BSTR 136             // B tile row stride (halfs)
#define A_ST (128 * ASTR)
#define B_ST (32 * BSTR)
#define GEMM3_SMEM ((2 * A_ST * 2 + 2 * B_ST * 2) * 2)   // 75776 bytes
#define GEMM2_SMEM ((2 * A_ST + 2 * B_ST * 2) * 2)       // 55296 bytes

// ---------------------------------------------------------------------------
// fp16x3 GEMM (AhBh + AhBl + AlBh): Q,K columns only (feed fp8 quantizer —
// boundary flips amplify GEMM error ~16x, so full accuracy required here).
// ---------------------------------------------------------------------------
__global__ void __launch_bounds__(256, 2)
gemm_f16x3(const __half* __restrict__ Ahp, const __half* __restrict__ Alp,
           const __half* __restrict__ Bhp, const __half* __restrict__ Blp,
           float* __restrict__ Cm, int M, int N, int K) {
    extern __shared__ __half sm[];
    __half* As_h = sm;
    __half* As_l = sm + 2 * A_ST;
    __half* Bs_h = sm + 4 * A_ST;
    __half* Bs_l = sm + 4 * A_ST + 2 * B_ST;

    const int bm = blockIdx.y * 128;
    const int bn = blockIdx.x * 128;
    const int tid = threadIdx.x;
    const int wid = tid >> 5, lane = tid & 31;
    const int gid = lane >> 2, tig = lane & 3;
    const int wm = (wid & 3) * 32;
    const int wn = (wid >> 2) * 64;
    const int lrow = lane & 15;

    float acc[2][8][4];
#pragma unroll
    for (int i = 0; i < 2; i++)
#pragma unroll
        for (int j = 0; j < 8; j++)
#pragma unroll
            for (int t = 0; t < 4; t++) acc[i][j][t] = 0.f;

    auto issue = [&](int kt, int buf) {
#pragma unroll
        for (int l = 0; l < 2; l++) {
            int id = tid + l * 256;
            int r = id >> 2, c8 = (id & 3) * 8;
            cp16(&As_h[buf * A_ST + r * ASTR + c8], &Ahp[(size_t)(bm + r) * K + kt + c8]);
            cp16(&As_l[buf * A_ST + r * ASTR + c8], &Alp[(size_t)(bm + r) * K + kt + c8]);
            int br_ = id >> 4, bc8 = (id & 15) * 8;
            cp16(&Bs_h[buf * B_ST + br_ * BSTR + bc8], &Bhp[(size_t)(kt + br_) * N + bn + bc8]);
            cp16(&Bs_l[buf * B_ST + br_ * BSTR + bc8], &Blp[(size_t)(kt + br_) * N + bn + bc8]);
        }
    };

    issue(0, 0);
    CP_COMMIT;
    CP_WAIT0;
    __syncthreads();

    int buf = 0;
    for (int kt = 0; kt < K; kt += 32) {
        if (kt + 32 < K) issue(kt + 32, buf ^ 1);
        CP_COMMIT;

        const unsigned* awh = (const unsigned*)(As_h + buf * A_ST);
        const unsigned* awl = (const unsigned*)(As_l + buf * A_ST);
        const __half* bsh = Bs_h + buf * B_ST;
        const __half* bsl = Bs_l + buf * B_ST;

#pragma unroll
        for (int ks = 0; ks < 2; ks++) {
            unsigned Af[2][4], Alf[2][4];
#pragma unroll
            for (int mt = 0; mt < 2; mt++) {
                int r0 = wm + mt * 16 + gid;
                int base = ks * 8 + tig;
                Af[mt][0]  = awh[r0 * 20 + base];
                Af[mt][1]  = awh[(r0 + 8) * 20 + base];
                Af[mt][2]  = awh[r0 * 20 + base + 4];
                Af[mt][3]  = awh[(r0 + 8) * 20 + base + 4];
                Alf[mt][0] = awl[r0 * 20 + base];
                Alf[mt][1] = awl[(r0 + 8) * 20 + base];
                Alf[mt][2] = awl[r0 * 20 + base + 4];
                Alf[mt][3] = awl[(r0 + 8) * 20 + base + 4];
            }
#pragma unroll
            for (int nt = 0; nt < 8; nt++) {
                unsigned bh0, bh1, bl0, bl1;
                ldsm_x2t(bh0, bh1, &bsh[(ks * 16 + lrow) * BSTR + wn + nt * 8]);
                ldsm_x2t(bl0, bl1, &bsl[(ks * 16 + lrow) * BSTR + wn + nt * 8]);
                mma_f16(acc[0][nt], Af[0],  bh0, bh1);
                mma_f16(acc[1][nt], Af[1],  bh0, bh1);
                mma_f16(acc[0][nt], Af[0],  bl0, bl1);
                mma_f16(acc[1][nt], Af[1],  bl0, bl1);
                mma_f16(acc[0][nt], Alf[0], bh0, bh1);
                mma_f16(acc[1][nt], Alf[1], bh0, bh1);
            }
        }
        CP_WAIT0;
        __syncthreads();
        buf ^= 1;
    }

#pragma unroll
    for (int mt = 0; mt < 2; mt++)
#pragma unroll
        for (int nt = 0; nt < 8; nt++) {
            int r = bm + wm + mt * 16 + gid;
            int c = bn + wn + nt * 8 + 2 * tig;
            Cm[(size_t)r * N + c]           = acc[mt][nt][0];
            Cm[(size_t)r * N + c + 1]       = acc[mt][nt][1];
            Cm[(size_t)(r + 8) * N + c]     = acc[mt][nt][2];
            Cm[(size_t)(r + 8) * N + c + 1] = acc[mt][nt][3];
        }
}

// ---------------------------------------------------------------------------
// fp16x2 GEMM (Ah(Bh+Bl)) + fp32 bias epilogue: proj (downstream of quantizers)
// ---------------------------------------------------------------------------
__global__ void __launch_bounds__(256, 2)
gemm_f16x2(const __half* __restrict__ Ahp,
           const __half* __restrict__ Bhp, const __half* __restrict__ Blp,
           const float* __restrict__ bias, float* __restrict__ Cm,
           int M, int N, int K) {
    extern __shared__ __half sm[];
    __half* As   = sm;
    __half* Bs_h = sm + 2 * A_ST;
    __half* Bs_l = sm + 2 * A_ST + 2 * B_ST;

    const int bm = blockIdx.y * 128;
    const int bn = blockIdx.x * 128;
    const int tid = threadIdx.x;
    const int wid = tid >> 5, lane = tid & 31;
    const int gid = lane >> 2, tig = lane & 3;
    const int wm = (wid & 3) * 32;
    const int wn = (wid >> 2) * 64;
    const int lrow = lane & 15;

    float acc[2][8][4];
#pragma unroll
    for (int i = 0; i < 2; i++)
#pragma unroll
        for (int j = 0; j < 8; j++)
#pragma unroll
            for (int t = 0; t < 4; t++) acc[i][j][t] = 0.f;

    auto issue = [&](int kt, int buf) {
#pragma unroll
        for (int l = 0; l < 2; l++) {
            int id = tid + l * 256;
            int r = id >> 2, c8 = (id & 3) * 8;
            cp16(&As[buf * A_ST + r * ASTR + c8], &Ahp[(size_t)(bm + r) * K + kt + c8]);
            int br_ = id >> 4, bc8 = (id & 15) * 8;
            cp16(&Bs_h[buf * B_ST + br_ * BSTR + bc8], &Bhp[(size_t)(kt + br_) * N + bn + bc8]);
            cp16(&Bs_l[buf * B_ST + br_ * BSTR + bc8], &Blp[(size_t)(kt + br_) * N + bn + bc8]);
        }
    };

    issue(0, 0);
    CP_COMMIT;
    CP_WAIT0;
    __syncthreads();

    int buf = 0;
    for (int kt = 0; kt < K; kt += 32) {
        if (kt + 32 < K) issue(kt + 32, buf ^ 1);
        CP_COMMIT;

        const unsigned* aw = (const unsigned*)(As + buf * A_ST);
        const __half* bsh = Bs_h + buf * B_ST;
        const __half* bsl = Bs_l + buf * B_ST;

#pragma unroll
        for (int ks = 0; ks < 2; ks++) {
            unsigned Af[2][4];
#pragma unroll
            for (int mt = 0; mt < 2; mt++) {
                int r0 = wm + mt * 16 + gid;
                int base = ks * 8 + tig;
                Af[mt][0] = aw[r0 * 20 + base];
                Af[mt][1] = aw[(r0 + 8) * 20 + base];
                Af[mt][2] = aw[r0 * 20 + base + 4];
                Af[mt][3] = aw[(r0 + 8) * 20 + base + 4];
            }
#pragma unroll
            for (int nt = 0; nt < 8; nt++) {
                unsigned bh0, bh1, bl0, bl1;
                ldsm_x2t(bh0, bh1, &bsh[(ks * 16 + lrow) * BSTR + wn + nt * 8]);
                ldsm_x2t(bl0, bl1, &bsl[(ks * 16 + lrow) * BSTR + wn + nt * 8]);
                mma_f16(acc[0][nt], Af[0], bh0, bh1);
                mma_f16(acc[1][nt], Af[1], bh0, bh1);
                mma_f16(acc[0][nt], Af[0], bl0, bl1);
                mma_f16(acc[1][nt], Af[1], bl0, bl1);
            }
        }
        CP_WAIT0;
        __syncthreads();
        buf ^= 1;
    }

#pragma unroll
    for (int mt = 0; mt < 2; mt++)
#pragma unroll
        for (int nt = 0; nt < 8; nt++) {
            int r = bm + wm + mt * 16 + gid;
            int c = bn + wn + nt * 8 + 2 * tig;
            float b0 = bias[c], b1 = bias[c + 1];
            Cm[(size_t)r * N + c]           = acc[mt][nt][0] + b0;
            Cm[(size_t)r * N + c + 1]       = acc[mt][nt][1] + b1;
            Cm[(size_t)(r + 8) * N + c]     = acc[mt][nt][2] + b0;
            Cm[(size_t)(r + 8) * N + c + 1] = acc[mt][nt][3] + b1;
        }
}

// ---------------------------------------------------------------------------
// fp16x2 V-GEMM: computes V = x @ w_qkv[:, 2C:3C] with x2 accuracy and writes
// fp16 head-major [b,h,n,d] directly into g_v16 (replaces conv_v entirely).
// V tolerance: rounded to fp16 anyway; x2's 2.4e-4 is below that effect.
// B pointers passed pre-offset by +2C; Nstr is the 3C row stride.
// ---------------------------------------------------------------------------
__global__ void __launch_bounds__(256, 2)
gemm_v16(const __half* __restrict__ Ahp,
         const __half* __restrict__ Bhp, const __half* __restrict__ Blp,
         __half* __restrict__ Vout, int Nstr, int K) {
    extern __shared__ __half sm[];
    __half* As   = sm;
    __half* Bs_h = sm + 2 * A_ST;
    __half* Bs_l = sm + 2 * A_ST + 2 * B_ST;

    const int bm = blockIdx.y * 128;
    const int bn = blockIdx.x * 128;
    const int tid = threadIdx.x;
    const int wid = tid >> 5, lane = tid & 31;
    const int gid = lane >> 2, tig = lane & 3;
    const int wm = (wid & 3) * 32;
    const int wn = (wid >> 2) * 64;
    const int lrow = lane & 15;

    float acc[2][8][4];
#pragma unroll
    for (int i = 0; i < 2; i++)
#pragma unroll
        for (int j = 0; j < 8; j++)
#pragma unroll
            for (int t = 0; t < 4; t++) acc[i][j][t] = 0.f;

    auto issue = [&](int kt, int buf) {
#pragma unroll
        for (int l = 0; l < 2; l++) {
            int id = tid + l * 256;
            int r = id >> 2, c8 = (id & 3) * 8;
            cp16(&As[buf * A_ST + r * ASTR + c8], &Ahp[(size_t)(bm + r) * K + kt + c8]);
            int br_ = id >> 4, bc8 = (id & 15) * 8;
            cp16(&Bs_h[buf * B_ST + br_ * BSTR + bc8], &Bhp[(size_t)(kt + br_) * Nstr + bn + bc8]);
            cp16(&Bs_l[buf * B_ST + br_ * BSTR + bc8], &Blp[(size_t)(kt + br_) * Nstr + bn + bc8]);
        }
    };

    issue(0, 0);
    CP_COMMIT;
    CP_WAIT0;
    __syncthreads();

    int buf = 0;
    for (int kt = 0; kt < K; kt += 32) {
        if (kt + 32 < K) issue(kt + 32, buf ^ 1);
        CP_COMMIT;

        const unsigned* aw = (const unsigned*)(As + buf * A_ST);
        const __half* bsh = Bs_h + buf * B_ST;
        const __half* bsl = Bs_l + buf * B_ST;

#pragma unroll
        for (int ks = 0; ks < 2; ks++) {
            unsigned Af[2][4];
#pragma unroll
            for (int mt = 0; mt < 2; mt++) {
                int r0 = wm + mt * 16 + gid;
                int base = ks * 8 + tig;
                Af[mt][0] = aw[r0 * 20 + base];
                Af[mt][1] = aw[(r0 + 8) * 20 + base];
                Af[mt][2] = aw[r0 * 20 + base + 4];
                Af[mt][3] = aw[(r0 + 8) * 20 + base + 4];
            }
#pragma unroll
            for (int nt = 0; nt < 8; nt++) {
                unsigned bh0, bh1, bl0, bl1;
                ldsm_x2t(bh0, bh1, &bsh[(ks * 16 + lrow) * BSTR + wn + nt * 8]);
                ldsm_x2t(bl0, bl1, &bsl[(ks * 16 + lrow) * BSTR + wn + nt * 8]);
                mma_f16(acc[0][nt], Af[0], bh0, bh1);
                mma_f16(acc[1][nt], Af[1], bh0, bh1);
                mma_f16(acc[0][nt], Af[0], bl0, bl1);
                mma_f16(acc[1][nt], Af[1], bl0, bl1);
            }
        }
        CP_WAIT0;
        __syncthreads();
        buf ^= 1;
    }

    // epilogue: fp16 head-major [b,h,n,d]
#pragma unroll
    for (int mt = 0; mt < 2; mt++)
#pragma unroll
        for (int nt = 0; nt < 8; nt++) {
            int r = bm + wm + mt * 16 + gid;          // global row: b*2048 + n
            int c = bn + wn + nt * 8 + 2 * tig;       // v column: h*64 + d
            int b = r >> 11, n = r & 2047;
            int h = c >> 6, d = c & 63;
            size_t o0 = ((size_t)((b * H_ + h) * N_ + n)) * D_ + d;
            size_t o1 = ((size_t)((b * H_ + h) * N_ + n + 8)) * D_ + d;
            *(__half2*)&Vout[o0] = __floats2half2_rn(acc[mt][nt][0], acc[mt][nt][1]);
            *(__half2*)&Vout[o1] = __floats2half2_rn(acc[mt][nt][2], acc[mt][nt][3]);
        }
}

// ---------------------------------------------------------------------------
// amax: two-stage (q,k slabs only)
// ---------------------------------------------------------------------------
__global__ void amax_part() {
    const int part = blockIdx.x;
    const int bw = blockIdx.y;
    const int w = bw & 1;
    const int h = (bw >> 1) & 15;
    const int b = bw >> 5;
    __shared__ float red[256];
    float mx = 0.f;
    const int n0 = part * (N_ / 8);
    for (int i = threadIdx.x; i < (N_ / 8) * D_; i += 256) {
        int n = n0 + (i >> 6), d = i & 63;
        float v = g_qkv[((size_t)(b * N_ + n)) * (3 * C_) + w * C_ + h * D_ + d];
        mx = fmaxf(mx, fabsf(v));
    }
    red[threadIdx.x] = mx;
    __syncthreads();
    for (int s = 128; s; s >>= 1) {
        if (threadIdx.x < s) red[threadIdx.x] = fmaxf(red[threadIdx.x], red[threadIdx.x + s]);
        __syncthreads();
    }
    if (threadIdx.x == 0) g_part[bw * 8 + part] = red[0];
}

__global__ void amax_fin() {
    int bw = threadIdx.x;
    float mx = 0.f;
#pragma unroll
    for (int p = 0; p < 8; p++) mx = fmaxf(mx, g_part[bw * 8 + p]);
    float amax = fmaxf(mx, 1e-12f);
    g_scale[bw]  = 448.f / amax;
    g_iscale[bw] = amax / 448.f;
}

// ---------------------------------------------------------------------------
// fp8 quantize Q,K into head-major byte arrays
// ---------------------------------------------------------------------------
__global__ void quant_kernel() {
    int gid = blockIdx.x * blockDim.x + threadIdx.x;
    if (gid >= B_ * N_ * 2 * (C_ / 4)) return;
    int c4 = (gid & 255) * 4;
    int w  = (gid >> 8) & 1;
    int n  = (gid >> 9) & 2047;
    int b  = gid >> 20;
    int h  = c4 >> 6;
    int d  = c4 & 63;
    int si = (b * 16 + h) * 2 + w;
    float s = g_scale[si];
    size_t base = ((size_t)(b * N_ + n)) * (3 * C_) + w * C_ + c4;
    float4 v = *(const float4*)&g_qkv[base];
    unsigned u0 = __nv_cvt_float_to_fp8(v.x * s, __NV_SATFINITE, __NV_E4M3);
    unsigned u1 = __nv_cvt_float_to_fp8(v.y * s, __NV_SATFINITE, __NV_E4M3);
    unsigned u2 = __nv_cvt_float_to_fp8(v.z * s, __NV_SATFINITE, __NV_E4M3);
    unsigned u3 = __nv_cvt_float_to_fp8(v.w * s, __NV_SATFINITE, __NV_E4M3);
    unsigned word = u0 | (u1 << 8) | (u2 << 16) | (u3 << 24);
    unsigned char* dst = (w == 0) ? g_q8 : g_k8;
    *(unsigned*)&dst[((size_t)((b * 16 + h) * N_ + n)) * 64 + d] = word;
}

// ---------------------------------------------------------------------------
// Tensor-core causal flash attention. QK^T fp8, PV fp16.
// cp.async double-buffered K8/V16 tiles; work-balanced pairs {p, 31-p}.
// ---------------------------------------------------------------------------
#define KSTR 20     // K8 tile row stride in words
#define VSTRH 72    // V tile row stride in halfs
#define PSTRH 72    // P tile row stride in halfs

__global__ void flash_fp8() {
    const int pid = blockIdx.x, h = blockIdx.y, b = blockIdx.z;
    __shared__ unsigned Ks8[2][64 * KSTR];
    __shared__ __half Vs[2][64 * VSTRH];
    __shared__ __half Ps[64 * PSTRH];

    const int tid = threadIdx.x;
    const int w = tid >> 5, lane = tid & 31;
    const int gid = lane >> 2, tig = lane & 3;
    const int bh = b * H_ + h;
    const unsigned* q8 = (const unsigned*)(g_q8 + (size_t)bh * N_ * D_);
    const unsigned* k8 = (const unsigned*)(g_k8 + (size_t)bh * N_ * D_);
    const __half* v16 = g_v16 + (size_t)bh * N_ * D_;
    const float sc = g_iscale[bh * 2 + 0] * g_iscale[bh * 2 + 1] * 0.125f;

    const int prw0 = (w * 16 + gid) * (PSTRH / 2);
    const int prw1 = (w * 16 + gid + 8) * (PSTRH / 2);
    const int ph0 = (w * 16 + gid) * PSTRH;
    const int ph1 = (w * 16 + gid + 8) * PSTRH;

    auto issue = [&](int kt_, int st) {
        const int k0 = kt_ * 64;
#pragma unroll
        for (int l = 0; l < 2; l++) {
            int idx = tid + l * 128;
            int rr = idx >> 2, cc = (idx & 3) * 4;
            cp16(&Ks8[st][rr * KSTR + cc], &k8[(size_t)(k0 + rr) * 16 + cc]);
        }
#pragma unroll
        for (int l = 0; l < 4; l++) {
            int idx = tid + l * 128;
            int rr = idx >> 3, ch = idx & 7;
            cp16(&Vs[st][rr * VSTRH + ch * 8], &v16[(size_t)(k0 + rr) * 64 + ch * 8]);
        }
    };

    for (int rep = 0; rep < 2; rep++) {
        const int qt = rep ? (N_ / 64 - 1 - pid) : pid;
        const int q0 = qt * 64;
        const int r0 = q0 + w * 16 + gid;

        unsigned qa[2][4];
#pragma unroll
        for (int ks = 0; ks < 2; ks++) {
            qa[ks][0] = q8[r0 * 16 + tig + 8 * ks];
            qa[ks][1] = q8[(r0 + 8) * 16 + tig + 8 * ks];
            qa[ks][2] = q8[r0 * 16 + tig + 4 + 8 * ks];
            qa[ks][3] = q8[(r0 + 8) * 16 + tig + 4 + 8 * ks];
        }

        float m0 = -INFINITY, m1 = -INFINITY, l0 = 0.f, l1 = 0.f;
        float o[8][4];
#pragma unroll
        for (int nt = 0; nt < 8; nt++)
#pragma unroll
            for (int e = 0; e < 4; e++) o[nt][e] = 0.f;

        __syncthreads();
        issue(0, 0);
        CP_COMMIT;

        int st = 0;
        for (int kt = 0; kt <= qt; kt++) {
            if (kt < qt) {
                __syncthreads();
                issue(kt + 1, st ^ 1);
                CP_COMMIT;
                CP_WAIT1;
            } else {
                CP_WAIT0;
            }
            __syncthreads();

            float s[8][4];
#pragma unroll
            for (int nt = 0; nt < 8; nt++) {
                s[nt][0] = s[nt][1] = s[nt][2] = s[nt][3] = 0.f;
                const int col = nt * 8 + gid;
                unsigned b0 = Ks8[st][col * KSTR + tig];
                unsigned b1 = Ks8[st][col * KSTR + tig + 4];
                mma_e4m3(s[nt], qa[0], b0, b1);
                unsigned b2 = Ks8[st][col * KSTR + tig + 8];
                unsigned b3 = Ks8[st][col * KSTR + tig + 12];
                mma_e4m3(s[nt], qa[1], b2, b3);
            }
            const bool diag = (kt == qt);
#pragma unroll
            for (int nt = 0; nt < 8; nt++) {
                s[nt][0] *= sc; s[nt][1] *= sc; s[nt][2] *= sc; s[nt][3] *= sc;
                if (diag) {
                    int cl = nt * 8 + 2 * tig;
                    int rl0 = w * 16 + gid, rl1 = rl0 + 8;
                    if (cl > rl0)     s[nt][0] = -1e30f;
                    if (cl + 1 > rl0) s[nt][1] = -1e30f;
                    if (cl > rl1)     s[nt][2] = -1e30f;
                    if (cl + 1 > rl1) s[nt][3] = -1e30f;
                }
            }
            float mx0 = s[0][0], mx1 = s[0][2];
#pragma unroll
            for (int nt = 0; nt < 8; nt++) {
                mx0 = fmaxf(mx0, fmaxf(s[nt][0], s[nt][1]));
                mx1 = fmaxf(mx1, fmaxf(s[nt][2], s[nt][3]));
            }
            mx0 = fmaxf(mx0, __shfl_xor_sync(0xffffffffu, mx0, 1));
            mx0 = fmaxf(mx0, __shfl_xor_sync(0xffffffffu, mx0, 2));
            mx1 = fmaxf(mx1, __shfl_xor_sync(0xffffffffu, mx1, 1));
            mx1 = fmaxf(mx1, __shfl_xor_sync(0xffffffffu, mx1, 2));
            const float mn0 = fmaxf(m0, mx0), mn1 = fmaxf(m1, mx1);
            const float f0 = __expf(m0 - mn0), f1 = __expf(m1 - mn1);
            float sum0 = 0.f, sum1 = 0.f;
#pragma unroll
            for (int nt = 0; nt < 8; nt++) {
                float p0 = __expf(s[nt][0] - mn0);
                float p1 = __expf(s[nt][1] - mn0);
                float p2 = __expf(s[nt][2] - mn1);
                float p3 = __expf(s[nt][3] - mn1);
                sum0 += p0 + p1; sum1 += p2 + p3;
                *(__half2*)&Ps[ph0 + nt * 8 + 2 * tig] = __floats2half2_rn(p0, p1);
                *(__half2*)&Ps[ph1 + nt * 8 + 2 * tig] = __floats2half2_rn(p2, p3);
#pragma unroll
                for (int e = 0; e < 2; e++) { o[nt][e] *= f0; o[nt][e + 2] *= f1; }
            }
            sum0 += __shfl_xor_sync(0xffffffffu, sum0, 1);
            sum0 += __shfl_xor_sync(0xffffffffu, sum0, 2);
            sum1 += __shfl_xor_sync(0xffffffffu, sum1, 1);
            sum1 += __shfl_xor_sync(0xffffffffu, sum1, 2);
            l0 = l0 * f0 + sum0;
            l1 = l1 * f1 + sum1;
            m0 = mn0; m1 = mn1;
            __syncwarp();

            const unsigned* Pw = (const unsigned*)Ps;
#pragma unroll
            for (int kc = 0; kc < 4; kc++) {
                unsigned a[4];
                a[0] = Pw[prw0 + kc * 8 + tig];
                a[1] = Pw[prw1 + kc * 8 + tig];
                a[2] = Pw[prw0 + kc * 8 + tig + 4];
                a[3] = Pw[prw1 + kc * 8 + tig + 4];
#pragma unroll
                for (int nt = 0; nt < 8; nt++) {
                    unsigned b0, b1;
                    ldsm_x2t(b0, b1, &Vs[st][(kc * 16 + (lane & 15)) * VSTRH + nt * 8]);
                    mma_f16(o[nt], a, b0, b1);
                }
            }
            st ^= 1;
        }

        // epilogue: write O as fp16 hi only (proj x2 A operand)
        const float il0 = 1.f / l0, il1 = 1.f / l1;
#pragma unroll
        for (int nt = 0; nt < 8; nt++) {
            size_t c = h * D_ + nt * 8 + 2 * tig;
            size_t i0 = ((size_t)(b * N_ + r0)) * C_ + c;
            size_t i1 = ((size_t)(b * N_ + r0 + 8)) * C_ + c;
            *(__half2*)&g_atth[i0] = __floats2half2_rn(o[nt][0] * il0, o[nt][1] * il0);
            *(__half2*)&g_atth[i1] = __floats2half2_rn(o[nt][2] * il1, o[nt][3] * il1);
        }
    }
}

// ---------------------------------------------------------------------------
extern "C" void kernel_launch(void* const* d_in, const int* in_sizes, int n_in,
                              void* d_out, int out_size) {
    const float* x      = (const float*)d_in[0];   // [2,2048,1024]
    const float* w_qkv  = (const float*)d_in[1];   // [1024,3072]
    const float* w_proj = (const float*)d_in[2];   // [1024,1024]
    const float* b_proj = (const float*)d_in[3];   // [1024]
    float* out = (float*)d_out;                    // [2,2048,1024]

    float* qkv_ptr; cudaGetSymbolAddress((void**)&qkv_ptr, g_qkv);
    __half *xh, *xl, *wqh, *wql, *wph, *wpl, *ath, *v16p;
    cudaGetSymbolAddress((void**)&xh,  g_xh);
    cudaGetSymbolAddress((void**)&xl,  g_xl);
    cudaGetSymbolAddress((void**)&wqh, g_wqh);
    cudaGetSymbolAddress((void**)&wql, g_wql);
    cudaGetSymbolAddress((void**)&wph, g_wph);
    cudaGetSymbolAddress((void**)&wpl, g_wpl);
    cudaGetSymbolAddress((void**)&ath, g_atth);
    cudaGetSymbolAddress((void**)&v16p, g_v16);

    // dynamic smem opt-in (idempotent host attribute set)
    cudaFuncSetAttribute(gemm_f16x3, cudaFuncAttributeMaxDynamicSharedMemorySize, GEMM3_SMEM);
    cudaFuncSetAttribute(gemm_f16x2, cudaFuncAttributeMaxDynamicSharedMemorySize, GEMM2_SMEM);
    cudaFuncSetAttribute(gemm_v16,   cudaFuncAttributeMaxDynamicSharedMemorySize, GEMM2_SMEM);

    // 0) fp16 splits
    prep_split<<<(B_ * N_ * C_ / 4 + 255) / 256, 256>>>(x, xh, xl, B_ * N_ * C_ / 4);
    prep_split<<<(C_ * 3 * C_ / 4 + 255) / 256, 256>>>(w_qkv, wqh, wql, C_ * 3 * C_ / 4);
    prep_split<<<(C_ * C_ / 4 + 255) / 256, 256>>>(w_proj, wph, wpl, C_ * C_ / 4);

    // 1a) QK GEMM (fp16x3 — feeds fp8 quantizer): columns 0..2047
    {
        dim3 grid(2 * C_ / 128, (B_ * N_) / 128);
        gemm_f16x3<<<grid, 256, GEMM3_SMEM>>>(xh, xl, wqh, wql, qkv_ptr, B_ * N_, 3 * C_, C_);
    }
    // 1b) V GEMM (fp16x2, fp16 head-major epilogue): columns 2048..3071
    {
        dim3 grid(C_ / 128, (B_ * N_) / 128);
        gemm_v16<<<grid, 256, GEMM2_SMEM>>>(xh, wqh + 2 * C_, wql + 2 * C_, v16p, 3 * C_, C_);
    }
    // 2) amax -> scales
    {
        dim3 grid(8, 64);
        amax_part<<<grid, 256>>>();
        amax_fin<<<1, 64>>>();
    }
    // 3) fp8 quantize q,k
    quant_kernel<<<(B_ * N_ * 2 * (C_ / 4) + 255) / 256, 256>>>();
    // 4) tensor-core causal flash attention
    {
        dim3 grid(N_ / 128, H_, B_);
        flash_fp8<<<grid, 128>>>();
    }
    // 5) output projection + bias (fp16x2)
    {
        dim3 grid(C_ / 128, (B_ * N_) / 128);
        gemm_f16x2<<<grid, 256, GEMM2_SMEM>>>(ath, wph, wpl, b_proj, out, B_ * N_, C_, C_);
    }
}